// round 12
// baseline (speedup 1.0000x reference)
#include <cuda_runtime.h>
#include <math.h>

#define BB 8
#define TT 8192
#define DV 1024
#define DQ 768
#define KREP 6
#define NH 8
#define HD 128
#define CC 18
#define NB 2048
#define NBLK 128
#define PB 288     // k_post blocks (2 per SM, 288 <= 296)

// ---------------- scratch (no allocations allowed) ----------------
__device__ __align__(16) float g_pre[2 * BB * DV];
__device__ __align__(16) float g_h[2 * BB * DV];
__device__ __align__(16) float g_mu[BB * DV];
__device__ __align__(16) float g_isg[BB * DV];
__device__ __align__(16) float g_rep[BB * KREP * DV];
__device__ __align__(16) float g_qkv[BB * KREP * 3 * DV];
__device__ __align__(16) float g_ao[BB * KREP * DV];
__device__ float g_attnw[BB * NH * KREP * KREP];
__device__ unsigned g_cnt = 0, g_gen = 0;

__device__ __forceinline__ float warp_sum(float v) {
#pragma unroll
    for (int o = 16; o; o >>= 1) v += __shfl_xor_sync(0xffffffffu, v, o);
    return v;
}

// software grid barrier: nblk blocks, all co-resident
__device__ __forceinline__ void gbar(unsigned nblk) {
    __syncthreads();
    if (threadIdx.x == 0) {
        volatile unsigned* vgen = &g_gen;
        unsigned gen = *vgen;
        __threadfence();
        unsigned t = atomicAdd(&g_cnt, 1u);
        if (t == nblk - 1) {
            atomicExch(&g_cnt, 0u);
            __threadfence();
            atomicAdd(&g_gen, 1u);
        } else {
            while (*vgen == gen) { }
            __threadfence();
        }
    }
    __syncthreads();
}

// ================= kernel 1: MLP (lin1 -> LN -> lin2), persistent =================
__global__ __launch_bounds__(512, 1) void k_mlp(
    const float* __restrict__ qe,
    const float* __restrict__ mu_w1, const float* __restrict__ mu_b1,
    const float* __restrict__ mu_g,  const float* __restrict__ mu_bt,
    const float* __restrict__ mu_w2, const float* __restrict__ mu_b2,
    const float* __restrict__ sg_w1, const float* __restrict__ sg_b1,
    const float* __restrict__ sg_g,  const float* __restrict__ sg_bt,
    const float* __restrict__ sg_w2, const float* __restrict__ sg_b2,
    float* __restrict__ o_mu, float* __restrict__ o_sg) {

    __shared__ float red[16];
    __shared__ float sh_mean, sh_rstd;
    int tid = threadIdx.x, lane = tid & 31, wid = tid >> 5, blk = blockIdx.x;

    // ---- P0: Linear(768->1024) both branches: 16384 dots, 8/warp ----
    {
        int gw = blk * 16 + wid;  // 0..2047
#pragma unroll
        for (int d = 0; d < 8; d++) {
            int idx = gw * 8 + d;
            int br = idx >> 13;
            int rem = idx & 8191;
            int b = rem >> 10, o = rem & 1023;
            const float* w1 = br ? sg_w1 : mu_w1;
            const float* b1 = br ? sg_b1 : mu_b1;
            const float* x = qe + b * DQ;
            const float* wr = w1 + o * DQ;
            float acc = 0.f;
#pragma unroll
            for (int i = lane; i < DQ; i += 32) acc += wr[i] * x[i];
            acc = warp_sum(acc);
            if (lane == 0) g_pre[(br * BB + b) * DV + o] = acc + b1[o];
        }
    }
    gbar(NBLK);

    // ---- P1: LayerNorm + ReLU (blocks 0..15, one per (b,br)) ----
    if (blk < 16) {
        int b = blk >> 1, br = blk & 1;
        const float* src = g_pre + (br * BB + b) * DV;
        float v0 = src[tid], v1 = src[tid + 512];
        float s = warp_sum(v0 + v1);
        if (lane == 0) red[wid] = s;
        __syncthreads();
        if (tid == 0) {
            float m = 0.f;
            for (int i = 0; i < 16; i++) m += red[i];
            sh_mean = m / (float)DV;
        }
        __syncthreads();
        float m = sh_mean;
        float d0 = v0 - m, d1 = v1 - m;
        float vv = warp_sum(d0 * d0 + d1 * d1);
        if (lane == 0) red[wid] = vv;
        __syncthreads();
        if (tid == 0) {
            float q = 0.f;
            for (int i = 0; i < 16; i++) q += red[i];
            sh_rstd = rsqrtf(q / (float)DV + 1e-5f);
        }
        __syncthreads();
        float rstd = sh_rstd;
        const float* g  = br ? sg_g  : mu_g;
        const float* bt = br ? sg_bt : mu_bt;
        float* dst = g_h + (br * BB + b) * DV;
        dst[tid]       = fmaxf(d0 * rstd * g[tid]       + bt[tid], 0.f);
        dst[tid + 512] = fmaxf(d1 * rstd * g[tid + 512] + bt[tid + 512], 0.f);
    }
    gbar(NBLK);

    // ---- P2: Linear(1024->1024) + mu/softplus epilogue ----
    {
        int gw = blk * 16 + wid;
#pragma unroll
        for (int d = 0; d < 8; d++) {
            int idx = gw * 8 + d;
            int br = idx >> 13;
            int rem = idx & 8191;
            int b = rem >> 10, o = rem & 1023;
            const float* w2 = br ? sg_w2 : mu_w2;
            const float* b2 = br ? sg_b2 : mu_b2;
            const float* x = g_h + (br * BB + b) * DV;
            const float* wr = w2 + o * DV;
            float acc = 0.f;
#pragma unroll
            for (int i = lane; i < DV; i += 32) acc += wr[i] * x[i];
            acc = warp_sum(acc);
            if (lane == 0) {
                float val = acc + b2[o];
                if (br == 0) {
                    g_mu[b * DV + o] = val;
                    o_mu[b * DV + o] = val;
                } else {
                    float sp = fmaxf(val, 0.f) + log1pf(expf(-fabsf(val)));
                    float sg = sp + 1e-6f;
                    o_sg[b * DV + o] = sg;
                    g_isg[b * DV + o] = 1.f / sg;
                }
            }
        }
    }
}

// ================= kernel 2: Mahalanobis distance (wide grid, proven) =================
__global__ void k_dist(const float* __restrict__ vf, float* __restrict__ o_dist) {
    __shared__ float4 mus[DV / 4];
    __shared__ float4 iss[DV / 4];
    int b = blockIdx.y;
    int tid = threadIdx.x, lane = tid & 31, wid = tid >> 5;
    if (tid < 256) mus[tid] = ((const float4*)(g_mu + b * DV))[tid];
    else           iss[tid - 256] = ((const float4*)(g_isg + b * DV))[tid - 256];
    __syncthreads();

    int t0 = (blockIdx.x * 16 + wid) * 2;
    const float4* v0 = (const float4*)(vf + ((size_t)b * TT + t0) * DV);
    const float4* v1 = v0 + DV / 4;
    float a0 = 0.f, a1 = 0.f;
#pragma unroll
    for (int it = 0; it < 8; it++) {
        int i = lane + it * 32;
        float4 x0 = v0[i], x1 = v1[i], mm = mus[i], ss = iss[i];
        float d;
        d = x0.x - mm.x; a0 += d * d * ss.x;
        d = x0.y - mm.y; a0 += d * d * ss.y;
        d = x0.z - mm.z; a0 += d * d * ss.z;
        d = x0.w - mm.w; a0 += d * d * ss.w;
        d = x1.x - mm.x; a1 += d * d * ss.x;
        d = x1.y - mm.y; a1 += d * d * ss.y;
        d = x1.z - mm.z; a1 += d * d * ss.z;
        d = x1.w - mm.w; a1 += d * d * ss.w;
    }
    a0 = warp_sum(a0);
    a1 = warp_sum(a1);
    if (lane == 0) {
        o_dist[b * TT + t0]     = a0;
        o_dist[b * TT + t0 + 1] = a1;
    }
}

// ================= kernel 3: select (proven, 8 x 1024) =================
__device__ void radix_pass_s(const unsigned* __restrict__ keys,
                             int shift, int bits, bool first,
                             unsigned* hist, unsigned* wsum, unsigned* wpfx,
                             unsigned* sh_prefix, int* sh_k) {
    int tid = threadIdx.x, lane = tid & 31, wid = tid >> 5;
    hist[tid] = 0u;
    hist[tid + 1024] = 0u;
    __syncthreads();
    unsigned pfx = *sh_prefix;
    unsigned mask = (1u << bits) - 1u;
#pragma unroll
    for (int r = 0; r < 8; r++) {
        unsigned key = keys[tid + r * 1024];
        bool ok = first || ((key >> (shift + bits)) == pfx);
        if (ok) atomicAdd(&hist[(key >> shift) & mask], 1u);
    }
    __syncthreads();
    unsigned s0 = hist[tid * 2], s1 = hist[tid * 2 + 1];
    unsigned s = s0 + s1;
    unsigned inc = s;
#pragma unroll
    for (int o = 1; o < 32; o <<= 1) {
        unsigned n = __shfl_up_sync(0xffffffffu, inc, o);
        if (lane >= o) inc += n;
    }
    if (lane == 31) wsum[wid] = inc;
    __syncthreads();
    if (wid == 0) {
        unsigned v = wsum[lane];
        unsigned iw = v;
#pragma unroll
        for (int o = 1; o < 32; o <<= 1) {
            unsigned n = __shfl_up_sync(0xffffffffu, iw, o);
            if (lane >= o) iw += n;
        }
        wpfx[lane] = iw - v;
    }
    __syncthreads();
    unsigned base = wpfx[wid] + (inc - s);
    unsigned k = (unsigned)*sh_k;
    if (k >= base && k < base + s) {
        int bin = tid * 2;
        unsigned off = base;
        if (k >= off + s0) { off += s0; bin++; }
        *sh_prefix = (pfx << bits) | (unsigned)bin;
        *sh_k = (int)(k - off);
    }
    __syncthreads();
}

__global__ void k_select(const float* __restrict__ dist, const float* __restrict__ vf,
                         float* __restrict__ o_idx) {
    __shared__ unsigned keys[TT];
    __shared__ unsigned hist[NB];
    __shared__ unsigned wsum[32], wpfx[32];
    __shared__ unsigned sh_prefix;
    __shared__ int sh_k;
    __shared__ unsigned long long lessK[CC];
    __shared__ int eqIdx[64];
    __shared__ int sh_nless, sh_neq;
    __shared__ int sels[KREP];

    int b = blockIdx.x;
    int tid = threadIdx.x;
    const float* drow = dist + b * TT;

#pragma unroll
    for (int r = 0; r < 8; r++)
        keys[tid + r * 1024] = __float_as_uint(drow[tid + r * 1024]);
    if (tid == 0) { sh_prefix = 0u; sh_k = (TT - 1) / 2; }
    __syncthreads();

    radix_pass_s(keys, 21, 11, true,  hist, wsum, wpfx, &sh_prefix, &sh_k);
    radix_pass_s(keys, 10, 11, false, hist, wsum, wpfx, &sh_prefix, &sh_k);
    radix_pass_s(keys,  0, 10, false, hist, wsum, wpfx, &sh_prefix, &sh_k);
    float med = __uint_as_float(sh_prefix);
    __syncthreads();

#pragma unroll
    for (int r = 0; r < 8; r++) {
        int i = tid + r * 1024;
        keys[i] = __float_as_uint(fabsf(__uint_as_float(keys[i]) - med));
    }
    if (tid == 0) { sh_prefix = 0u; sh_k = CC - 1; sh_nless = 0; sh_neq = 0; }
    __syncthreads();

    radix_pass_s(keys, 21, 11, true,  hist, wsum, wpfx, &sh_prefix, &sh_k);
    radix_pass_s(keys, 10, 11, false, hist, wsum, wpfx, &sh_prefix, &sh_k);
    radix_pass_s(keys,  0, 10, false, hist, wsum, wpfx, &sh_prefix, &sh_k);
    unsigned vstar = sh_prefix;
    int n_eq_take = sh_k + 1;
    __syncthreads();

#pragma unroll
    for (int r = 0; r < 8; r++) {
        int i = tid + r * 1024;
        unsigned key = keys[i];
        if (key < vstar) {
            int p = atomicAdd(&sh_nless, 1);
            lessK[p] = ((unsigned long long)key << 13) | (unsigned)i;
        } else if (key == vstar) {
            int p = atomicAdd(&sh_neq, 1);
            if (p < 64) eqIdx[p] = i;
        }
    }
    __syncthreads();

    if (tid == 0) {
        int nless = sh_nless;
        int neq = sh_neq < 64 ? sh_neq : 64;
        for (int i = 1; i < nless; i++) {
            unsigned long long kv = lessK[i];
            int j = i - 1;
            while (j >= 0 && lessK[j] > kv) { lessK[j + 1] = lessK[j]; j--; }
            lessK[j + 1] = kv;
        }
        for (int i = 1; i < neq; i++) {
            int kv = eqIdx[i];
            int j = i - 1;
            while (j >= 0 && eqIdx[j] > kv) { eqIdx[j + 1] = eqIdx[j]; j--; }
            eqIdx[j + 1] = kv;
        }
        int cand[CC];
        for (int c = 0; c < nless; c++) cand[c] = (int)(lessK[c] & 0x1FFFull);
        for (int c = 0; c < n_eq_take && nless + c < CC; c++) cand[nless + c] = eqIdx[c];

        const float NINF = __int_as_float(0xff800000);
        float candf[CC], mind[CC];
        int sel[KREP];
        for (int c = 0; c < CC; c++) candf[c] = (float)cand[c];
        for (int c = 0; c < CC; c++) mind[c] = fabsf(candf[c] - candf[0]);
        mind[0] = NINF;
        sel[0] = cand[0];
        for (int sI = 1; sI < KREP; sI++) {
            int best = 0;
            float bm = NINF;
            for (int c = 0; c < CC; c++)
                if (mind[c] > bm) { bm = mind[c]; best = c; }
            sel[sI] = cand[best];
            float cb = candf[best];
            for (int c = 0; c < CC; c++) mind[c] = fminf(mind[c], fabsf(candf[c] - cb));
            mind[best] = NINF;
        }
        for (int sI = 0; sI < KREP; sI++) {
            sels[sI] = sel[sI];
            o_idx[b * KREP + sI] = (float)sel[sI];
        }
    }
    __syncthreads();

    for (int kk = 0; kk < KREP; kk++) {
        int t = sels[kk];
        const float* src = vf + ((size_t)b * TT + t) * DV;
        float* dst = g_rep + (b * KREP + kk) * DV;
        if (tid < DV) dst[tid] = src[tid];
    }
}

// ================= kernel 4: post — lane-per-output broadcast GEMM =================
// Block 256 thr = 8 warps = 4 row-chunks(4 rows) x 2 k-halves(64k of each 128-k tile).
// lane = output column (32 outputs per task). x read via same-address broadcast LDS,
// w via k-major transposed smem tile (float2-packed, pitch 33 -> conflict-free).
__device__ void gemm_phase(const float* __restrict__ x, const float* __restrict__ w,
                           const float* __restrict__ bias, float* __restrict__ out,
                           int ostride, int ogroups, int rgroups,
                           float* xs, float2* wt2, float* red) {
    int tid = threadIdx.x, lane = tid & 31, wid = tid >> 5;
    int chunk = wid >> 1, khalf = wid & 1;
    int ntask = ogroups * rgroups;
    for (int task = blockIdx.x; task < ntask; task += PB) {
        int og = task % ogroups, rg = task / ogroups;
        int obase = og * 32, rbase = rg * 16;
        float acc[4] = {0.f, 0.f, 0.f, 0.f};

        for (int kc = 0; kc < 8; kc++) {
            __syncthreads();
            // x tile: 16 rows x 128 k = 512 float4, 2 per thread
#pragma unroll
            for (int j = 0; j < 2; j++) {
                int i = tid + j * 256;
                int r = i >> 5, k4 = i & 31;
                ((float4*)xs)[i] =
                    *(const float4*)(x + (size_t)(rbase + r) * DV + kc * 128 + k4 * 4);
            }
            // w tile transposed: o = tid>>3 (0..31), kbase = (tid&7)*16
            {
                int o = tid >> 3, kbase = (tid & 7) * 16;
                const float4* wr =
                    (const float4*)(w + (size_t)(obase + o) * DV + kc * 128 + kbase);
                float4 a = wr[0], bq = wr[1], c = wr[2], d = wr[3];
                int k2 = kbase >> 1;
                wt2[(k2 + 0) * 33 + o] = make_float2(a.x, a.y);
                wt2[(k2 + 1) * 33 + o] = make_float2(a.z, a.w);
                wt2[(k2 + 2) * 33 + o] = make_float2(bq.x, bq.y);
                wt2[(k2 + 3) * 33 + o] = make_float2(bq.z, bq.w);
                wt2[(k2 + 4) * 33 + o] = make_float2(c.x, c.y);
                wt2[(k2 + 5) * 33 + o] = make_float2(c.z, c.w);
                wt2[(k2 + 6) * 33 + o] = make_float2(d.x, d.y);
                wt2[(k2 + 7) * 33 + o] = make_float2(d.z, d.w);
            }
            __syncthreads();
            // compute: rows chunk*4..+3, k = khalf*64 + kk
#pragma unroll
            for (int kk = 0; kk < 64; kk += 4) {
                int kl = khalf * 64 + kk;
                int k2 = kl >> 1;
                float2 wa = wt2[k2 * 33 + lane];
                float2 wb = wt2[(k2 + 1) * 33 + lane];
#pragma unroll
                for (int r = 0; r < 4; r++) {
                    float4 xb = *(const float4*)&xs[(chunk * 4 + r) * 128 + kl];
                    acc[r] += xb.x * wa.x + xb.y * wa.y + xb.z * wb.x + xb.w * wb.y;
                }
            }
        }
        // combine k-halves
        __syncthreads();
        if (khalf == 1) {
#pragma unroll
            for (int r = 0; r < 4; r++) red[(chunk * 4 + r) * 32 + lane] = acc[r];
        }
        __syncthreads();
        if (khalf == 0) {
            float bs = bias[obase + lane];
#pragma unroll
            for (int r = 0; r < 4; r++) {
                int row = rbase + chunk * 4 + r;
                out[(size_t)row * ostride + obase + lane] =
                    acc[r] + red[(chunk * 4 + r) * 32 + lane] + bs;
            }
        }
    }
}

__global__ __launch_bounds__(256, 2) void k_post(
    const float* __restrict__ in_w,  const float* __restrict__ in_b,
    const float* __restrict__ out_w, const float* __restrict__ out_b,
    float* __restrict__ o_ref, float* __restrict__ o_attn) {

    __shared__ __align__(16) float xs[16 * 128];   // 8KB
    __shared__ __align__(16) float2 wt2[64 * 33];  // 16.9KB
    __shared__ float red[16 * 32];                 // 2KB
    int tid = threadIdx.x, lane = tid & 31, wid = tid >> 5, blk = blockIdx.x;

    // ---- P0: QKV GEMM: 96 ogroups x 3 rgroups = 288 tasks ----
    gemm_phase(g_rep, in_w, in_b, g_qkv, 3 * DV, 96, 3, xs, wt2, red);
    gbar(PB);

    // ---- P1: attention per (b,h) (blocks 0..63) ----
    if (blk < BB * NH) {
        int b = blk >> 3, h = blk & 7;
        float* qs = xs;
        float* ks = xs + KREP * HD;
        float* vs = (float*)wt2;
        for (int i = tid; i < KREP * HD; i += 256) {
            int row = i >> 7, d = i & 127;
            const float* base = g_qkv + (b * KREP + row) * 3 * DV + h * HD + d;
            qs[i] = base[0];
            ks[i] = base[DV];
            vs[i] = base[2 * DV];
        }
        __syncthreads();
        if (wid < KREP) {
            int i = wid;
            float sc[KREP];
            const float scale = 0.08838834764831845f;  // 1/sqrt(128)
            for (int j = 0; j < KREP; j++) {
                float acc = 0.f;
#pragma unroll
                for (int m = 0; m < 4; m++)
                    acc += qs[i * HD + lane + 32 * m] * ks[j * HD + lane + 32 * m];
                acc = warp_sum(acc);
                sc[j] = acc * scale;
            }
            float mx = sc[0];
            for (int j = 1; j < KREP; j++) mx = fmaxf(mx, sc[j]);
            float den = 0.f;
            for (int j = 0; j < KREP; j++) { sc[j] = expf(sc[j] - mx); den += sc[j]; }
            float rden = 1.f / den;
            for (int j = 0; j < KREP; j++) sc[j] *= rden;
            if (lane < KREP)
                g_attnw[((b * NH + h) * KREP + i) * KREP + lane] = sc[lane];
            for (int d = lane; d < HD; d += 32) {
                float o = 0.f;
                for (int j = 0; j < KREP; j++) o += sc[j] * vs[j * HD + d];
                g_ao[(b * KREP + i) * DV + h * HD + d] = o;
            }
        }
    }
    gbar(PB);

    // ---- P2: attn-weight head-mean (blocks 64..71) + output projection (96 tasks) ----
    if (blk >= 64 && blk < 64 + BB && tid < KREP * KREP) {
        int b = blk - 64;
        float s = 0.f;
        for (int h = 0; h < NH; h++) s += g_attnw[(b * NH + h) * KREP * KREP + tid];
        o_attn[b * KREP * KREP + tid] = s * (1.f / (float)NH);
    }
    gemm_phase(g_ao, out_w, out_b, o_ref, DV, 32, 3, xs, wt2, red);
}

// ---------------- launcher ----------------
extern "C" void kernel_launch(void* const* d_in, const int* in_sizes, int n_in,
                              void* d_out, int out_size) {
    const float* vf    = (const float*)d_in[0];
    const float* qe    = (const float*)d_in[1];
    const float* mu_w1 = (const float*)d_in[2];
    const float* mu_b1 = (const float*)d_in[3];
    const float* mu_g  = (const float*)d_in[4];
    const float* mu_bt = (const float*)d_in[5];
    const float* mu_w2 = (const float*)d_in[6];
    const float* mu_b2 = (const float*)d_in[7];
    const float* sg_w1 = (const float*)d_in[8];
    const float* sg_b1 = (const float*)d_in[9];
    const float* sg_g  = (const float*)d_in[10];
    const float* sg_bt = (const float*)d_in[11];
    const float* sg_w2 = (const float*)d_in[12];
    const float* sg_b2 = (const float*)d_in[13];
    const float* in_w  = (const float*)d_in[14];
    const float* in_b  = (const float*)d_in[15];
    const float* out_w = (const float*)d_in[16];
    const float* out_b = (const float*)d_in[17];

    float* out = (float*)d_out;
    float* o_ref  = out;           // [8,6,1024]  49152
    float* o_idx  = out + 49152;   // [8,6]       48
    float* o_dist = out + 49200;   // [8,8192]    65536
    float* o_mu   = out + 114736;  // [8,1024]    8192
    float* o_sg   = out + 122928;  // [8,1024]    8192
    float* o_attn = out + 131120;  // [8,6,6]     288

    k_mlp<<<NBLK, 512>>>(qe, mu_w1, mu_b1, mu_g, mu_bt, mu_w2, mu_b2,
                         sg_w1, sg_b1, sg_g, sg_bt, sg_w2, sg_b2, o_mu, o_sg);
    k_dist<<<dim3(TT / 32, BB), 512>>>(vf, o_dist);
    k_select<<<BB, 1024>>>(o_dist, vf, o_idx);
    k_post<<<PB, 256>>>(in_w, in_b, out_w, out_b, o_ref, o_attn);
}

// round 13
// speedup vs baseline: 1.0619x; 1.0619x over previous
#include <cuda_runtime.h>
#include <math.h>

#define BB 8
#define TT 8192
#define DV 1024
#define DQ 768
#define KREP 6
#define NH 8
#define HD 128
#define CC 18
#define NB 2048
#define NBLK 128
#define PB 148          // k_post blocks: 1/SM (192KB smem)
#define PTHR 768        // k_post threads (24 warps)
#define PSMEM (48 * DV * 4)   // 192KB dynamic smem

// ---------------- scratch (no allocations allowed) ----------------
__device__ __align__(16) float g_pre[2 * BB * DV];
__device__ __align__(16) float g_h[2 * BB * DV];
__device__ __align__(16) float g_mu[BB * DV];
__device__ __align__(16) float g_isg[BB * DV];
__device__ __align__(16) float g_rep[BB * KREP * DV];
__device__ __align__(16) float g_qkv[BB * KREP * 3 * DV];
__device__ __align__(16) float g_ao[BB * KREP * DV];
__device__ float g_attnw[BB * NH * KREP * KREP];
__device__ unsigned g_cnt = 0, g_gen = 0;

__device__ __forceinline__ float warp_sum(float v) {
#pragma unroll
    for (int o = 16; o; o >>= 1) v += __shfl_xor_sync(0xffffffffu, v, o);
    return v;
}

// software grid barrier: nblk blocks, all co-resident
__device__ __forceinline__ void gbar(unsigned nblk) {
    __syncthreads();
    if (threadIdx.x == 0) {
        volatile unsigned* vgen = &g_gen;
        unsigned gen = *vgen;
        __threadfence();
        unsigned t = atomicAdd(&g_cnt, 1u);
        if (t == nblk - 1) {
            atomicExch(&g_cnt, 0u);
            __threadfence();
            atomicAdd(&g_gen, 1u);
        } else {
            while (*vgen == gen) { }
            __threadfence();
        }
    }
    __syncthreads();
}

// ================= kernel 1: MLP (lin1 -> LN -> lin2), persistent =================
__global__ __launch_bounds__(512, 1) void k_mlp(
    const float* __restrict__ qe,
    const float* __restrict__ mu_w1, const float* __restrict__ mu_b1,
    const float* __restrict__ mu_g,  const float* __restrict__ mu_bt,
    const float* __restrict__ mu_w2, const float* __restrict__ mu_b2,
    const float* __restrict__ sg_w1, const float* __restrict__ sg_b1,
    const float* __restrict__ sg_g,  const float* __restrict__ sg_bt,
    const float* __restrict__ sg_w2, const float* __restrict__ sg_b2,
    float* __restrict__ o_mu, float* __restrict__ o_sg) {

    __shared__ float red[16];
    __shared__ float sh_mean, sh_rstd;
    int tid = threadIdx.x, lane = tid & 31, wid = tid >> 5, blk = blockIdx.x;

    // ---- P0: Linear(768->1024) both branches: 16384 dots, 8/warp ----
    {
        int gw = blk * 16 + wid;  // 0..2047
#pragma unroll
        for (int d = 0; d < 8; d++) {
            int idx = gw * 8 + d;
            int br = idx >> 13;
            int rem = idx & 8191;
            int b = rem >> 10, o = rem & 1023;
            const float* w1 = br ? sg_w1 : mu_w1;
            const float* b1 = br ? sg_b1 : mu_b1;
            const float* x = qe + b * DQ;
            const float* wr = w1 + o * DQ;
            float acc = 0.f;
#pragma unroll
            for (int i = lane; i < DQ; i += 32) acc += wr[i] * x[i];
            acc = warp_sum(acc);
            if (lane == 0) g_pre[(br * BB + b) * DV + o] = acc + b1[o];
        }
    }
    gbar(NBLK);

    // ---- P1: LayerNorm + ReLU (blocks 0..15, one per (b,br)) ----
    if (blk < 16) {
        int b = blk >> 1, br = blk & 1;
        const float* src = g_pre + (br * BB + b) * DV;
        float v0 = src[tid], v1 = src[tid + 512];
        float s = warp_sum(v0 + v1);
        if (lane == 0) red[wid] = s;
        __syncthreads();
        if (tid == 0) {
            float m = 0.f;
            for (int i = 0; i < 16; i++) m += red[i];
            sh_mean = m / (float)DV;
        }
        __syncthreads();
        float m = sh_mean;
        float d0 = v0 - m, d1 = v1 - m;
        float vv = warp_sum(d0 * d0 + d1 * d1);
        if (lane == 0) red[wid] = vv;
        __syncthreads();
        if (tid == 0) {
            float q = 0.f;
            for (int i = 0; i < 16; i++) q += red[i];
            sh_rstd = rsqrtf(q / (float)DV + 1e-5f);
        }
        __syncthreads();
        float rstd = sh_rstd;
        const float* g  = br ? sg_g  : mu_g;
        const float* bt = br ? sg_bt : mu_bt;
        float* dst = g_h + (br * BB + b) * DV;
        dst[tid]       = fmaxf(d0 * rstd * g[tid]       + bt[tid], 0.f);
        dst[tid + 512] = fmaxf(d1 * rstd * g[tid + 512] + bt[tid + 512], 0.f);
    }
    gbar(NBLK);

    // ---- P2: Linear(1024->1024) + mu/softplus epilogue ----
    {
        int gw = blk * 16 + wid;
#pragma unroll
        for (int d = 0; d < 8; d++) {
            int idx = gw * 8 + d;
            int br = idx >> 13;
            int rem = idx & 8191;
            int b = rem >> 10, o = rem & 1023;
            const float* w2 = br ? sg_w2 : mu_w2;
            const float* b2 = br ? sg_b2 : mu_b2;
            const float* x = g_h + (br * BB + b) * DV;
            const float* wr = w2 + o * DV;
            float acc = 0.f;
#pragma unroll
            for (int i = lane; i < DV; i += 32) acc += wr[i] * x[i];
            acc = warp_sum(acc);
            if (lane == 0) {
                float val = acc + b2[o];
                if (br == 0) {
                    g_mu[b * DV + o] = val;
                    o_mu[b * DV + o] = val;
                } else {
                    float sp = fmaxf(val, 0.f) + log1pf(expf(-fabsf(val)));
                    float sg = sp + 1e-6f;
                    o_sg[b * DV + o] = sg;
                    g_isg[b * DV + o] = 1.f / sg;
                }
            }
        }
    }
}

// ================= kernel 2: Mahalanobis distance (wide grid, proven) =================
__global__ void k_dist(const float* __restrict__ vf, float* __restrict__ o_dist) {
    __shared__ float4 mus[DV / 4];
    __shared__ float4 iss[DV / 4];
    int b = blockIdx.y;
    int tid = threadIdx.x, lane = tid & 31, wid = tid >> 5;
    if (tid < 256) mus[tid] = ((const float4*)(g_mu + b * DV))[tid];
    else           iss[tid - 256] = ((const float4*)(g_isg + b * DV))[tid - 256];
    __syncthreads();

    int t0 = (blockIdx.x * 16 + wid) * 2;
    const float4* v0 = (const float4*)(vf + ((size_t)b * TT + t0) * DV);
    const float4* v1 = v0 + DV / 4;
    float a0 = 0.f, a1 = 0.f;
#pragma unroll
    for (int it = 0; it < 8; it++) {
        int i = lane + it * 32;
        float4 x0 = v0[i], x1 = v1[i], mm = mus[i], ss = iss[i];
        float d;
        d = x0.x - mm.x; a0 += d * d * ss.x;
        d = x0.y - mm.y; a0 += d * d * ss.y;
        d = x0.z - mm.z; a0 += d * d * ss.z;
        d = x0.w - mm.w; a0 += d * d * ss.w;
        d = x1.x - mm.x; a1 += d * d * ss.x;
        d = x1.y - mm.y; a1 += d * d * ss.y;
        d = x1.z - mm.z; a1 += d * d * ss.z;
        d = x1.w - mm.w; a1 += d * d * ss.w;
    }
    a0 = warp_sum(a0);
    a1 = warp_sum(a1);
    if (lane == 0) {
        o_dist[b * TT + t0]     = a0;
        o_dist[b * TT + t0 + 1] = a1;
    }
}

// ================= kernel 3: select (proven, 8 x 1024) =================
__device__ void radix_pass_s(const unsigned* __restrict__ keys,
                             int shift, int bits, bool first,
                             unsigned* hist, unsigned* wsum, unsigned* wpfx,
                             unsigned* sh_prefix, int* sh_k) {
    int tid = threadIdx.x, lane = tid & 31, wid = tid >> 5;
    hist[tid] = 0u;
    hist[tid + 1024] = 0u;
    __syncthreads();
    unsigned pfx = *sh_prefix;
    unsigned mask = (1u << bits) - 1u;
#pragma unroll
    for (int r = 0; r < 8; r++) {
        unsigned key = keys[tid + r * 1024];
        bool ok = first || ((key >> (shift + bits)) == pfx);
        if (ok) atomicAdd(&hist[(key >> shift) & mask], 1u);
    }
    __syncthreads();
    unsigned s0 = hist[tid * 2], s1 = hist[tid * 2 + 1];
    unsigned s = s0 + s1;
    unsigned inc = s;
#pragma unroll
    for (int o = 1; o < 32; o <<= 1) {
        unsigned n = __shfl_up_sync(0xffffffffu, inc, o);
        if (lane >= o) inc += n;
    }
    if (lane == 31) wsum[wid] = inc;
    __syncthreads();
    if (wid == 0) {
        unsigned v = wsum[lane];
        unsigned iw = v;
#pragma unroll
        for (int o = 1; o < 32; o <<= 1) {
            unsigned n = __shfl_up_sync(0xffffffffu, iw, o);
            if (lane >= o) iw += n;
        }
        wpfx[lane] = iw - v;
    }
    __syncthreads();
    unsigned base = wpfx[wid] + (inc - s);
    unsigned k = (unsigned)*sh_k;
    if (k >= base && k < base + s) {
        int bin = tid * 2;
        unsigned off = base;
        if (k >= off + s0) { off += s0; bin++; }
        *sh_prefix = (pfx << bits) | (unsigned)bin;
        *sh_k = (int)(k - off);
    }
    __syncthreads();
}

__global__ void k_select(const float* __restrict__ dist, const float* __restrict__ vf,
                         float* __restrict__ o_idx) {
    __shared__ unsigned keys[TT];
    __shared__ unsigned hist[NB];
    __shared__ unsigned wsum[32], wpfx[32];
    __shared__ unsigned sh_prefix;
    __shared__ int sh_k;
    __shared__ unsigned long long lessK[CC];
    __shared__ int eqIdx[64];
    __shared__ int sh_nless, sh_neq;
    __shared__ int sels[KREP];

    int b = blockIdx.x;
    int tid = threadIdx.x;
    const float* drow = dist + b * TT;

#pragma unroll
    for (int r = 0; r < 8; r++)
        keys[tid + r * 1024] = __float_as_uint(drow[tid + r * 1024]);
    if (tid == 0) { sh_prefix = 0u; sh_k = (TT - 1) / 2; }
    __syncthreads();

    radix_pass_s(keys, 21, 11, true,  hist, wsum, wpfx, &sh_prefix, &sh_k);
    radix_pass_s(keys, 10, 11, false, hist, wsum, wpfx, &sh_prefix, &sh_k);
    radix_pass_s(keys,  0, 10, false, hist, wsum, wpfx, &sh_prefix, &sh_k);
    float med = __uint_as_float(sh_prefix);
    __syncthreads();

#pragma unroll
    for (int r = 0; r < 8; r++) {
        int i = tid + r * 1024;
        keys[i] = __float_as_uint(fabsf(__uint_as_float(keys[i]) - med));
    }
    if (tid == 0) { sh_prefix = 0u; sh_k = CC - 1; sh_nless = 0; sh_neq = 0; }
    __syncthreads();

    radix_pass_s(keys, 21, 11, true,  hist, wsum, wpfx, &sh_prefix, &sh_k);
    radix_pass_s(keys, 10, 11, false, hist, wsum, wpfx, &sh_prefix, &sh_k);
    radix_pass_s(keys,  0, 10, false, hist, wsum, wpfx, &sh_prefix, &sh_k);
    unsigned vstar = sh_prefix;
    int n_eq_take = sh_k + 1;
    __syncthreads();

#pragma unroll
    for (int r = 0; r < 8; r++) {
        int i = tid + r * 1024;
        unsigned key = keys[i];
        if (key < vstar) {
            int p = atomicAdd(&sh_nless, 1);
            lessK[p] = ((unsigned long long)key << 13) | (unsigned)i;
        } else if (key == vstar) {
            int p = atomicAdd(&sh_neq, 1);
            if (p < 64) eqIdx[p] = i;
        }
    }
    __syncthreads();

    if (tid == 0) {
        int nless = sh_nless;
        int neq = sh_neq < 64 ? sh_neq : 64;
        for (int i = 1; i < nless; i++) {
            unsigned long long kv = lessK[i];
            int j = i - 1;
            while (j >= 0 && lessK[j] > kv) { lessK[j + 1] = lessK[j]; j--; }
            lessK[j + 1] = kv;
        }
        for (int i = 1; i < neq; i++) {
            int kv = eqIdx[i];
            int j = i - 1;
            while (j >= 0 && eqIdx[j] > kv) { eqIdx[j + 1] = eqIdx[j]; j--; }
            eqIdx[j + 1] = kv;
        }
        int cand[CC];
        for (int c = 0; c < nless; c++) cand[c] = (int)(lessK[c] & 0x1FFFull);
        for (int c = 0; c < n_eq_take && nless + c < CC; c++) cand[nless + c] = eqIdx[c];

        const float NINF = __int_as_float(0xff800000);
        float candf[CC], mind[CC];
        int sel[KREP];
        for (int c = 0; c < CC; c++) candf[c] = (float)cand[c];
        for (int c = 0; c < CC; c++) mind[c] = fabsf(candf[c] - candf[0]);
        mind[0] = NINF;
        sel[0] = cand[0];
        for (int sI = 1; sI < KREP; sI++) {
            int best = 0;
            float bm = NINF;
            for (int c = 0; c < CC; c++)
                if (mind[c] > bm) { bm = mind[c]; best = c; }
            sel[sI] = cand[best];
            float cb = candf[best];
            for (int c = 0; c < CC; c++) mind[c] = fminf(mind[c], fabsf(candf[c] - cb));
            mind[best] = NINF;
        }
        for (int sI = 0; sI < KREP; sI++) {
            sels[sI] = sel[sI];
            o_idx[b * KREP + sI] = (float)sel[sI];
        }
    }
    __syncthreads();

    for (int kk = 0; kk < KREP; kk++) {
        int t = sels[kk];
        const float* src = vf + ((size_t)b * TT + t) * DV;
        float* dst = g_rep + (b * KREP + kk) * DV;
        if (tid < DV) dst[tid] = src[tid];
    }
}

// ================= kernel 4: post — x-resident-in-smem GEMM, zero k-loop syncs ===========
// Warp task = (2 outputs, 16-row chunk). Per kc: 2 w float4 from L2 (prefetch +1),
// 16 x float4 from smem, 128 FFMA. acc[2][16]=32 regs. No per-kc barriers.
__device__ void gemm_phase(const float4* __restrict__ xs4, const float* __restrict__ w,
                           const float* __restrict__ bias, float* __restrict__ out,
                           int ostride, int nout) {
    int tid = threadIdx.x, lane = tid & 31, wid = tid >> 5;
    int og_count = nout >> 1;
    int ntask = og_count * 3;                  // 3 row-chunks of 16
    int gw = blockIdx.x * (PTHR / 32) + wid;   // global warp id
    for (int task = gw; task < ntask; task += PB * (PTHR / 32)) {
        int og = task % og_count, rch = task / og_count;
        int o0 = og * 2, rbase = rch * 16;
        const float4* w0p = (const float4*)(w + (size_t)o0 * DV);
        const float4* w1p = (const float4*)(w + (size_t)(o0 + 1) * DV);

        float acc0[16], acc1[16];
#pragma unroll
        for (int r = 0; r < 16; r++) { acc0[r] = 0.f; acc1[r] = 0.f; }

        float4 w0 = w0p[lane], w1 = w1p[lane];
#pragma unroll
        for (int kc = 0; kc < 8; kc++) {
            float4 nw0, nw1;
            if (kc < 7) { nw0 = w0p[(kc + 1) * 32 + lane]; nw1 = w1p[(kc + 1) * 32 + lane]; }
            const float4* xrow = xs4 + (size_t)rbase * 256 + kc * 32 + lane;
#pragma unroll
            for (int r = 0; r < 16; r++) {
                float4 xv = xrow[(size_t)r * 256];
                acc0[r] += w0.x * xv.x + w0.y * xv.y + w0.z * xv.z + w0.w * xv.w;
                acc1[r] += w1.x * xv.x + w1.y * xv.y + w1.z * xv.z + w1.w * xv.w;
            }
            if (kc < 7) { w0 = nw0; w1 = nw1; }
        }
        float bs0 = bias[o0], bs1 = bias[o0 + 1];
#pragma unroll
        for (int r = 0; r < 16; r++) {
            float s0 = warp_sum(acc0[r]);
            float s1 = warp_sum(acc1[r]);
            if (lane == r) {
                float* dst = out + (size_t)(rbase + r) * ostride;
                dst[o0]     = s0 + bs0;
                dst[o0 + 1] = s1 + bs1;
            }
        }
    }
}

__global__ __launch_bounds__(PTHR, 1) void k_post(
    const float* __restrict__ in_w,  const float* __restrict__ in_b,
    const float* __restrict__ out_w, const float* __restrict__ out_b,
    float* __restrict__ o_ref, float* __restrict__ o_attn) {

    extern __shared__ __align__(16) float sdyn[];   // 48*1024 floats = 192KB
    float4* xs4 = (float4*)sdyn;
    int tid = threadIdx.x, lane = tid & 31, wid = tid >> 5, blk = blockIdx.x;

    // stage x = g_rep once (12288 float4, 16/thread)
#pragma unroll
    for (int j = 0; j < 16; j++)
        xs4[tid + j * PTHR] = ((const float4*)g_rep)[tid + j * PTHR];
    __syncthreads();

    // ---- P0: QKV GEMM (1536 ogroups x 3 rchunks = 4608 tasks) ----
    gemm_phase(xs4, in_w, in_b, g_qkv, 3 * DV, 3 * DV);
    gbar(PB);

    // ---- P1: attention per (b,h) (blocks 0..63); tiles overlay sdyn ----
    if (blk < BB * NH) {
        int b = blk >> 3, h = blk & 7;
        float* qs = sdyn;
        float* ks = sdyn + KREP * HD;
        float* vs = sdyn + 2 * KREP * HD;
        for (int i = tid; i < KREP * HD; i += PTHR) {
            int row = i >> 7, d = i & 127;
            const float* base = g_qkv + (b * KREP + row) * 3 * DV + h * HD + d;
            qs[i] = base[0];
            ks[i] = base[DV];
            vs[i] = base[2 * DV];
        }
        __syncthreads();
        if (wid < KREP) {
            int i = wid;
            float sc[KREP];
            const float scale = 0.08838834764831845f;  // 1/sqrt(128)
            for (int j = 0; j < KREP; j++) {
                float acc = 0.f;
#pragma unroll
                for (int m = 0; m < 4; m++)
                    acc += qs[i * HD + lane + 32 * m] * ks[j * HD + lane + 32 * m];
                acc = warp_sum(acc);
                sc[j] = acc * scale;
            }
            float mx = sc[0];
            for (int j = 1; j < KREP; j++) mx = fmaxf(mx, sc[j]);
            float den = 0.f;
            for (int j = 0; j < KREP; j++) { sc[j] = expf(sc[j] - mx); den += sc[j]; }
            float rden = 1.f / den;
            for (int j = 0; j < KREP; j++) sc[j] *= rden;
            if (lane < KREP)
                g_attnw[((b * NH + h) * KREP + i) * KREP + lane] = sc[lane];
            for (int d = lane; d < HD; d += 32) {
                float o = 0.f;
                for (int j = 0; j < KREP; j++) o += sc[j] * vs[j * HD + d];
                g_ao[(b * KREP + i) * DV + h * HD + d] = o;
            }
        }
    }
    gbar(PB);

    // ---- P2: attn-weight head-mean (blocks 64..71), restage x = g_ao, oproj ----
    if (blk >= 64 && blk < 64 + BB && tid < KREP * KREP) {
        int b = blk - 64;
        float s = 0.f;
        for (int h = 0; h < NH; h++) s += g_attnw[(b * NH + h) * KREP * KREP + tid];
        o_attn[b * KREP * KREP + tid] = s * (1.f / (float)NH);
    }
    __syncthreads();
#pragma unroll
    for (int j = 0; j < 16; j++)
        xs4[tid + j * PTHR] = ((const float4*)g_ao)[tid + j * PTHR];
    __syncthreads();
    gemm_phase(xs4, out_w, out_b, o_ref, DV, DV);
}

// ---------------- launcher ----------------
extern "C" void kernel_launch(void* const* d_in, const int* in_sizes, int n_in,
                              void* d_out, int out_size) {
    const float* vf    = (const float*)d_in[0];
    const float* qe    = (const float*)d_in[1];
    const float* mu_w1 = (const float*)d_in[2];
    const float* mu_b1 = (const float*)d_in[3];
    const float* mu_g  = (const float*)d_in[4];
    const float* mu_bt = (const float*)d_in[5];
    const float* mu_w2 = (const float*)d_in[6];
    const float* mu_b2 = (const float*)d_in[7];
    const float* sg_w1 = (const float*)d_in[8];
    const float* sg_b1 = (const float*)d_in[9];
    const float* sg_g  = (const float*)d_in[10];
    const float* sg_bt = (const float*)d_in[11];
    const float* sg_w2 = (const float*)d_in[12];
    const float* sg_b2 = (const float*)d_in[13];
    const float* in_w  = (const float*)d_in[14];
    const float* in_b  = (const float*)d_in[15];
    const float* out_w = (const float*)d_in[16];
    const float* out_b = (const float*)d_in[17];

    float* out = (float*)d_out;
    float* o_ref  = out;           // [8,6,1024]  49152
    float* o_idx  = out + 49152;   // [8,6]       48
    float* o_dist = out + 49200;   // [8,8192]    65536
    float* o_mu   = out + 114736;  // [8,1024]    8192
    float* o_sg   = out + 122928;  // [8,1024]    8192
    float* o_attn = out + 131120;  // [8,6,6]     288

    static int attr_set = 0;
    if (!attr_set) {
        cudaFuncSetAttribute(k_post, cudaFuncAttributeMaxDynamicSharedMemorySize, PSMEM);
        attr_set = 1;
    }

    k_mlp<<<NBLK, 512>>>(qe, mu_w1, mu_b1, mu_g, mu_bt, mu_w2, mu_b2,
                         sg_w1, sg_b1, sg_g, sg_bt, sg_w2, sg_b2, o_mu, o_sg);
    k_dist<<<dim3(TT / 32, BB), 512>>>(vf, o_dist);
    k_select<<<BB, 1024>>>(o_dist, vf, o_idx);
    k_post<<<PB, PTHR, PSMEM>>>(in_w, in_b, out_w, out_b, o_ref, o_attn);
}

// round 14
// speedup vs baseline: 1.1181x; 1.0529x over previous
#include <cuda_runtime.h>
#include <math.h>

#define BB 8
#define TT 8192
#define DV 1024
#define DQ 768
#define KREP 6
#define NH 8
#define HD 128
#define CC 18
#define NB 2048
#define NBLK 128
#define PB 148          // k_post blocks: 1/SM (192KB smem)
#define PTHR 512        // k_post threads (16 warps)
#define PSMEM (48 * DV * 4)   // 192KB dynamic smem

// ---------------- scratch (no allocations allowed) ----------------
__device__ __align__(16) float g_pre[2 * BB * DV];
__device__ __align__(16) float g_h[2 * BB * DV];
__device__ __align__(16) float g_mu[BB * DV];
__device__ __align__(16) float g_isg[BB * DV];
__device__ __align__(16) float g_rep[BB * KREP * DV];
__device__ __align__(16) float g_qkv[BB * KREP * 3 * DV];
__device__ __align__(16) float g_ao[BB * KREP * DV];
__device__ float g_attnw[BB * NH * KREP * KREP];
__device__ unsigned g_cnt = 0, g_gen = 0;

__device__ __forceinline__ float warp_sum(float v) {
#pragma unroll
    for (int o = 16; o; o >>= 1) v += __shfl_xor_sync(0xffffffffu, v, o);
    return v;
}

// software grid barrier: nblk blocks, all co-resident
__device__ __forceinline__ void gbar(unsigned nblk) {
    __syncthreads();
    if (threadIdx.x == 0) {
        volatile unsigned* vgen = &g_gen;
        unsigned gen = *vgen;
        __threadfence();
        unsigned t = atomicAdd(&g_cnt, 1u);
        if (t == nblk - 1) {
            atomicExch(&g_cnt, 0u);
            __threadfence();
            atomicAdd(&g_gen, 1u);
        } else {
            while (*vgen == gen) { }
            __threadfence();
        }
    }
    __syncthreads();
}

// ================= kernel 1: MLP (lin1 -> LN -> lin2), persistent =================
__global__ __launch_bounds__(512, 1) void k_mlp(
    const float* __restrict__ qe,
    const float* __restrict__ mu_w1, const float* __restrict__ mu_b1,
    const float* __restrict__ mu_g,  const float* __restrict__ mu_bt,
    const float* __restrict__ mu_w2, const float* __restrict__ mu_b2,
    const float* __restrict__ sg_w1, const float* __restrict__ sg_b1,
    const float* __restrict__ sg_g,  const float* __restrict__ sg_bt,
    const float* __restrict__ sg_w2, const float* __restrict__ sg_b2,
    float* __restrict__ o_mu, float* __restrict__ o_sg) {

    __shared__ float red[16];
    __shared__ float sh_mean, sh_rstd;
    int tid = threadIdx.x, lane = tid & 31, wid = tid >> 5, blk = blockIdx.x;

    // ---- P0: Linear(768->1024) both branches: 16384 dots, 8/warp ----
    {
        int gw = blk * 16 + wid;  // 0..2047
#pragma unroll
        for (int d = 0; d < 8; d++) {
            int idx = gw * 8 + d;
            int br = idx >> 13;
            int rem = idx & 8191;
            int b = rem >> 10, o = rem & 1023;
            const float* w1 = br ? sg_w1 : mu_w1;
            const float* b1 = br ? sg_b1 : mu_b1;
            const float* x = qe + b * DQ;
            const float* wr = w1 + o * DQ;
            float acc = 0.f;
#pragma unroll
            for (int i = lane; i < DQ; i += 32) acc += wr[i] * x[i];
            acc = warp_sum(acc);
            if (lane == 0) g_pre[(br * BB + b) * DV + o] = acc + b1[o];
        }
    }
    gbar(NBLK);

    // ---- P1: LayerNorm + ReLU (blocks 0..15, one per (b,br)) ----
    if (blk < 16) {
        int b = blk >> 1, br = blk & 1;
        const float* src = g_pre + (br * BB + b) * DV;
        float v0 = src[tid], v1 = src[tid + 512];
        float s = warp_sum(v0 + v1);
        if (lane == 0) red[wid] = s;
        __syncthreads();
        if (tid == 0) {
            float m = 0.f;
            for (int i = 0; i < 16; i++) m += red[i];
            sh_mean = m / (float)DV;
        }
        __syncthreads();
        float m = sh_mean;
        float d0 = v0 - m, d1 = v1 - m;
        float vv = warp_sum(d0 * d0 + d1 * d1);
        if (lane == 0) red[wid] = vv;
        __syncthreads();
        if (tid == 0) {
            float q = 0.f;
            for (int i = 0; i < 16; i++) q += red[i];
            sh_rstd = rsqrtf(q / (float)DV + 1e-5f);
        }
        __syncthreads();
        float rstd = sh_rstd;
        const float* g  = br ? sg_g  : mu_g;
        const float* bt = br ? sg_bt : mu_bt;
        float* dst = g_h + (br * BB + b) * DV;
        dst[tid]       = fmaxf(d0 * rstd * g[tid]       + bt[tid], 0.f);
        dst[tid + 512] = fmaxf(d1 * rstd * g[tid + 512] + bt[tid + 512], 0.f);
    }
    gbar(NBLK);

    // ---- P2: Linear(1024->1024) + mu/softplus epilogue ----
    {
        int gw = blk * 16 + wid;
#pragma unroll
        for (int d = 0; d < 8; d++) {
            int idx = gw * 8 + d;
            int br = idx >> 13;
            int rem = idx & 8191;
            int b = rem >> 10, o = rem & 1023;
            const float* w2 = br ? sg_w2 : mu_w2;
            const float* b2 = br ? sg_b2 : mu_b2;
            const float* x = g_h + (br * BB + b) * DV;
            const float* wr = w2 + o * DV;
            float acc = 0.f;
#pragma unroll
            for (int i = lane; i < DV; i += 32) acc += wr[i] * x[i];
            acc = warp_sum(acc);
            if (lane == 0) {
                float val = acc + b2[o];
                if (br == 0) {
                    g_mu[b * DV + o] = val;
                    o_mu[b * DV + o] = val;
                } else {
                    float sp = fmaxf(val, 0.f) + log1pf(expf(-fabsf(val)));
                    float sg = sp + 1e-6f;
                    o_sg[b * DV + o] = sg;
                    g_isg[b * DV + o] = 1.f / sg;
                }
            }
        }
    }
}

// ================= kernel 2: Mahalanobis distance (wide grid, proven) =================
__global__ void k_dist(const float* __restrict__ vf, float* __restrict__ o_dist) {
    __shared__ float4 mus[DV / 4];
    __shared__ float4 iss[DV / 4];
    int b = blockIdx.y;
    int tid = threadIdx.x, lane = tid & 31, wid = tid >> 5;
    if (tid < 256) mus[tid] = ((const float4*)(g_mu + b * DV))[tid];
    else           iss[tid - 256] = ((const float4*)(g_isg + b * DV))[tid - 256];
    __syncthreads();

    int t0 = (blockIdx.x * 16 + wid) * 2;
    const float4* v0 = (const float4*)(vf + ((size_t)b * TT + t0) * DV);
    const float4* v1 = v0 + DV / 4;
    float a0 = 0.f, a1 = 0.f;
#pragma unroll
    for (int it = 0; it < 8; it++) {
        int i = lane + it * 32;
        float4 x0 = v0[i], x1 = v1[i], mm = mus[i], ss = iss[i];
        float d;
        d = x0.x - mm.x; a0 += d * d * ss.x;
        d = x0.y - mm.y; a0 += d * d * ss.y;
        d = x0.z - mm.z; a0 += d * d * ss.z;
        d = x0.w - mm.w; a0 += d * d * ss.w;
        d = x1.x - mm.x; a1 += d * d * ss.x;
        d = x1.y - mm.y; a1 += d * d * ss.y;
        d = x1.z - mm.z; a1 += d * d * ss.z;
        d = x1.w - mm.w; a1 += d * d * ss.w;
    }
    a0 = warp_sum(a0);
    a1 = warp_sum(a1);
    if (lane == 0) {
        o_dist[b * TT + t0]     = a0;
        o_dist[b * TT + t0 + 1] = a1;
    }
}

// ================= kernel 3: select (proven, 8 x 1024) =================
__device__ void radix_pass_s(const unsigned* __restrict__ keys,
                             int shift, int bits, bool first,
                             unsigned* hist, unsigned* wsum, unsigned* wpfx,
                             unsigned* sh_prefix, int* sh_k) {
    int tid = threadIdx.x, lane = tid & 31, wid = tid >> 5;
    hist[tid] = 0u;
    hist[tid + 1024] = 0u;
    __syncthreads();
    unsigned pfx = *sh_prefix;
    unsigned mask = (1u << bits) - 1u;
#pragma unroll
    for (int r = 0; r < 8; r++) {
        unsigned key = keys[tid + r * 1024];
        bool ok = first || ((key >> (shift + bits)) == pfx);
        if (ok) atomicAdd(&hist[(key >> shift) & mask], 1u);
    }
    __syncthreads();
    unsigned s0 = hist[tid * 2], s1 = hist[tid * 2 + 1];
    unsigned s = s0 + s1;
    unsigned inc = s;
#pragma unroll
    for (int o = 1; o < 32; o <<= 1) {
        unsigned n = __shfl_up_sync(0xffffffffu, inc, o);
        if (lane >= o) inc += n;
    }
    if (lane == 31) wsum[wid] = inc;
    __syncthreads();
    if (wid == 0) {
        unsigned v = wsum[lane];
        unsigned iw = v;
#pragma unroll
        for (int o = 1; o < 32; o <<= 1) {
            unsigned n = __shfl_up_sync(0xffffffffu, iw, o);
            if (lane >= o) iw += n;
        }
        wpfx[lane] = iw - v;
    }
    __syncthreads();
    unsigned base = wpfx[wid] + (inc - s);
    unsigned k = (unsigned)*sh_k;
    if (k >= base && k < base + s) {
        int bin = tid * 2;
        unsigned off = base;
        if (k >= off + s0) { off += s0; bin++; }
        *sh_prefix = (pfx << bits) | (unsigned)bin;
        *sh_k = (int)(k - off);
    }
    __syncthreads();
}

__global__ void k_select(const float* __restrict__ dist, const float* __restrict__ vf,
                         float* __restrict__ o_idx) {
    __shared__ unsigned keys[TT];
    __shared__ unsigned hist[NB];
    __shared__ unsigned wsum[32], wpfx[32];
    __shared__ unsigned sh_prefix;
    __shared__ int sh_k;
    __shared__ unsigned long long lessK[CC];
    __shared__ int eqIdx[64];
    __shared__ int sh_nless, sh_neq;
    __shared__ int sels[KREP];

    int b = blockIdx.x;
    int tid = threadIdx.x;
    const float* drow = dist + b * TT;

#pragma unroll
    for (int r = 0; r < 8; r++)
        keys[tid + r * 1024] = __float_as_uint(drow[tid + r * 1024]);
    if (tid == 0) { sh_prefix = 0u; sh_k = (TT - 1) / 2; }
    __syncthreads();

    radix_pass_s(keys, 21, 11, true,  hist, wsum, wpfx, &sh_prefix, &sh_k);
    radix_pass_s(keys, 10, 11, false, hist, wsum, wpfx, &sh_prefix, &sh_k);
    radix_pass_s(keys,  0, 10, false, hist, wsum, wpfx, &sh_prefix, &sh_k);
    float med = __uint_as_float(sh_prefix);
    __syncthreads();

#pragma unroll
    for (int r = 0; r < 8; r++) {
        int i = tid + r * 1024;
        keys[i] = __float_as_uint(fabsf(__uint_as_float(keys[i]) - med));
    }
    if (tid == 0) { sh_prefix = 0u; sh_k = CC - 1; sh_nless = 0; sh_neq = 0; }
    __syncthreads();

    radix_pass_s(keys, 21, 11, true,  hist, wsum, wpfx, &sh_prefix, &sh_k);
    radix_pass_s(keys, 10, 11, false, hist, wsum, wpfx, &sh_prefix, &sh_k);
    radix_pass_s(keys,  0, 10, false, hist, wsum, wpfx, &sh_prefix, &sh_k);
    unsigned vstar = sh_prefix;
    int n_eq_take = sh_k + 1;
    __syncthreads();

#pragma unroll
    for (int r = 0; r < 8; r++) {
        int i = tid + r * 1024;
        unsigned key = keys[i];
        if (key < vstar) {
            int p = atomicAdd(&sh_nless, 1);
            lessK[p] = ((unsigned long long)key << 13) | (unsigned)i;
        } else if (key == vstar) {
            int p = atomicAdd(&sh_neq, 1);
            if (p < 64) eqIdx[p] = i;
        }
    }
    __syncthreads();

    if (tid == 0) {
        int nless = sh_nless;
        int neq = sh_neq < 64 ? sh_neq : 64;
        for (int i = 1; i < nless; i++) {
            unsigned long long kv = lessK[i];
            int j = i - 1;
            while (j >= 0 && lessK[j] > kv) { lessK[j + 1] = lessK[j]; j--; }
            lessK[j + 1] = kv;
        }
        for (int i = 1; i < neq; i++) {
            int kv = eqIdx[i];
            int j = i - 1;
            while (j >= 0 && eqIdx[j] > kv) { eqIdx[j + 1] = eqIdx[j]; j--; }
            eqIdx[j + 1] = kv;
        }
        int cand[CC];
        for (int c = 0; c < nless; c++) cand[c] = (int)(lessK[c] & 0x1FFFull);
        for (int c = 0; c < n_eq_take && nless + c < CC; c++) cand[nless + c] = eqIdx[c];

        const float NINF = __int_as_float(0xff800000);
        float candf[CC], mind[CC];
        int sel[KREP];
        for (int c = 0; c < CC; c++) candf[c] = (float)cand[c];
        for (int c = 0; c < CC; c++) mind[c] = fabsf(candf[c] - candf[0]);
        mind[0] = NINF;
        sel[0] = cand[0];
        for (int sI = 1; sI < KREP; sI++) {
            int best = 0;
            float bm = NINF;
            for (int c = 0; c < CC; c++)
                if (mind[c] > bm) { bm = mind[c]; best = c; }
            sel[sI] = cand[best];
            float cb = candf[best];
            for (int c = 0; c < CC; c++) mind[c] = fminf(mind[c], fabsf(candf[c] - cb));
            mind[best] = NINF;
        }
        for (int sI = 0; sI < KREP; sI++) {
            sels[sI] = sel[sI];
            o_idx[b * KREP + sI] = (float)sel[sI];
        }
    }
    __syncthreads();

    for (int kk = 0; kk < KREP; kk++) {
        int t = sels[kk];
        const float* src = vf + ((size_t)b * TT + t) * DV;
        float* dst = g_rep + (b * KREP + kk) * DV;
        if (tid < DV) dst[tid] = src[tid];
    }
}

// ================= kernel 4: post — x-resident-in-smem GEMM, zero k-loop syncs ===========
// Warp task = (OPW outputs, 16-row chunk). Per kc: OPW w-float4 from L2 (prefetch +1),
// 16 x-float4 from smem, 64*OPW FFMA. No per-kc barriers.
template <int OPW>
__device__ void gemm_phase(const float4* __restrict__ xs4, const float* __restrict__ w,
                           const float* __restrict__ bias, float* __restrict__ out,
                           int ostride, int nout) {
    int tid = threadIdx.x, lane = tid & 31, wid = tid >> 5;
    int og_count = nout / OPW;
    int ntask = og_count * 3;                  // 3 row-chunks of 16
    int gw = blockIdx.x * (PTHR / 32) + wid;   // global warp id
    for (int task = gw; task < ntask; task += PB * (PTHR / 32)) {
        int og = task % og_count, rch = task / og_count;
        int o0 = og * OPW, rbase = rch * 16;
        const float4* wp[OPW];
#pragma unroll
        for (int j = 0; j < OPW; j++) wp[j] = (const float4*)(w + (size_t)(o0 + j) * DV);

        float acc[OPW][16];
#pragma unroll
        for (int j = 0; j < OPW; j++)
#pragma unroll
            for (int r = 0; r < 16; r++) acc[j][r] = 0.f;

        float4 wc[OPW], wn[OPW];
#pragma unroll
        for (int j = 0; j < OPW; j++) wc[j] = wp[j][lane];
#pragma unroll
        for (int kc = 0; kc < 8; kc++) {
            if (kc < 7) {
#pragma unroll
                for (int j = 0; j < OPW; j++) wn[j] = wp[j][(kc + 1) * 32 + lane];
            }
            const float4* xrow = xs4 + (size_t)rbase * 256 + kc * 32 + lane;
#pragma unroll
            for (int r = 0; r < 16; r++) {
                float4 xv = xrow[(size_t)r * 256];
#pragma unroll
                for (int j = 0; j < OPW; j++)
                    acc[j][r] += wc[j].x * xv.x + wc[j].y * xv.y +
                                 wc[j].z * xv.z + wc[j].w * xv.w;
            }
            if (kc < 7) {
#pragma unroll
                for (int j = 0; j < OPW; j++) wc[j] = wn[j];
            }
        }
        float bs[OPW];
#pragma unroll
        for (int j = 0; j < OPW; j++) bs[j] = bias[o0 + j];
#pragma unroll
        for (int r = 0; r < 16; r++) {
            float s[OPW];
#pragma unroll
            for (int j = 0; j < OPW; j++) s[j] = warp_sum(acc[j][r]);
            if (lane == r) {
                float* dst = out + (size_t)(rbase + r) * ostride + o0;
#pragma unroll
                for (int j = 0; j < OPW; j++) dst[j] = s[j] + bs[j];
            }
        }
    }
}

__global__ __launch_bounds__(PTHR, 1) void k_post(
    const float* __restrict__ in_w,  const float* __restrict__ in_b,
    const float* __restrict__ out_w, const float* __restrict__ out_b,
    float* __restrict__ o_ref, float* __restrict__ o_attn) {

    extern __shared__ __align__(16) float sdyn[];   // 48*1024 floats = 192KB
    float4* xs4 = (float4*)sdyn;
    int tid = threadIdx.x, lane = tid & 31, wid = tid >> 5, blk = blockIdx.x;

    // stage x = g_rep once (12288 float4, 24/thread)
#pragma unroll
    for (int j = 0; j < 24; j++)
        xs4[tid + j * PTHR] = ((const float4*)g_rep)[tid + j * PTHR];
    __syncthreads();

    // ---- P0: QKV GEMM (768 ogroups x 3 rchunks = 2304 tasks, one round) ----
    gemm_phase<4>(xs4, in_w, in_b, g_qkv, 3 * DV, 3 * DV);
    gbar(PB);

    // ---- P1: attention per (b,h) (blocks 0..63); tiles overlay sdyn ----
    if (blk < BB * NH) {
        int b = blk >> 3, h = blk & 7;
        float* qs = sdyn;
        float* ks = sdyn + KREP * HD;
        float* vs = sdyn + 2 * KREP * HD;
        for (int i = tid; i < KREP * HD; i += PTHR) {
            int row = i >> 7, d = i & 127;
            const float* base = g_qkv + (b * KREP + row) * 3 * DV + h * HD + d;
            qs[i] = base[0];
            ks[i] = base[DV];
            vs[i] = base[2 * DV];
        }
        __syncthreads();
        if (wid < KREP) {
            int i = wid;
            float sc[KREP];
            const float scale = 0.08838834764831845f;  // 1/sqrt(128)
            for (int j = 0; j < KREP; j++) {
                float acc = 0.f;
#pragma unroll
                for (int m = 0; m < 4; m++)
                    acc += qs[i * HD + lane + 32 * m] * ks[j * HD + lane + 32 * m];
                acc = warp_sum(acc);
                sc[j] = acc * scale;
            }
            float mx = sc[0];
            for (int j = 1; j < KREP; j++) mx = fmaxf(mx, sc[j]);
            float den = 0.f;
            for (int j = 0; j < KREP; j++) { sc[j] = expf(sc[j] - mx); den += sc[j]; }
            float rden = 1.f / den;
            for (int j = 0; j < KREP; j++) sc[j] *= rden;
            if (lane < KREP)
                g_attnw[((b * NH + h) * KREP + i) * KREP + lane] = sc[lane];
            for (int d = lane; d < HD; d += 32) {
                float o = 0.f;
                for (int j = 0; j < KREP; j++) o += sc[j] * vs[j * HD + d];
                g_ao[(b * KREP + i) * DV + h * HD + d] = o;
            }
        }
    }
    gbar(PB);

    // ---- P2: attn-weight head-mean (blocks 64..71), restage x = g_ao, oproj ----
    if (blk >= 64 && blk < 64 + BB && tid < KREP * KREP) {
        int b = blk - 64;
        float s = 0.f;
        for (int h = 0; h < NH; h++) s += g_attnw[(b * NH + h) * KREP * KREP + tid];
        o_attn[b * KREP * KREP + tid] = s * (1.f / (float)NH);
    }
    __syncthreads();
#pragma unroll
    for (int j = 0; j < 24; j++)
        xs4[tid + j * PTHR] = ((const float4*)g_ao)[tid + j * PTHR];
    __syncthreads();
    gemm_phase<2>(xs4, out_w, out_b, o_ref, DV, DV);
}

// ---------------- launcher ----------------
extern "C" void kernel_launch(void* const* d_in, const int* in_sizes, int n_in,
                              void* d_out, int out_size) {
    const float* vf    = (const float*)d_in[0];
    const float* qe    = (const float*)d_in[1];
    const float* mu_w1 = (const float*)d_in[2];
    const float* mu_b1 = (const float*)d_in[3];
    const float* mu_g  = (const float*)d_in[4];
    const float* mu_bt = (const float*)d_in[5];
    const float* mu_w2 = (const float*)d_in[6];
    const float* mu_b2 = (const float*)d_in[7];
    const float* sg_w1 = (const float*)d_in[8];
    const float* sg_b1 = (const float*)d_in[9];
    const float* sg_g  = (const float*)d_in[10];
    const float* sg_bt = (const float*)d_in[11];
    const float* sg_w2 = (const float*)d_in[12];
    const float* sg_b2 = (const float*)d_in[13];
    const float* in_w  = (const float*)d_in[14];
    const float* in_b  = (const float*)d_in[15];
    const float* out_w = (const float*)d_in[16];
    const float* out_b = (const float*)d_in[17];

    float* out = (float*)d_out;
    float* o_ref  = out;           // [8,6,1024]  49152
    float* o_idx  = out + 49152;   // [8,6]       48
    float* o_dist = out + 49200;   // [8,8192]    65536
    float* o_mu   = out + 114736;  // [8,1024]    8192
    float* o_sg   = out + 122928;  // [8,1024]    8192
    float* o_attn = out + 131120;  // [8,6,6]     288

    static int attr_set = 0;
    if (!attr_set) {
        cudaFuncSetAttribute(k_post, cudaFuncAttributeMaxDynamicSharedMemorySize, PSMEM);
        attr_set = 1;
    }

    k_mlp<<<NBLK, 512>>>(qe, mu_w1, mu_b1, mu_g, mu_bt, mu_w2, mu_b2,
                         sg_w1, sg_b1, sg_g, sg_bt, sg_w2, sg_b2, o_mu, o_sg);
    k_dist<<<dim3(TT / 32, BB), 512>>>(vf, o_dist);
    k_select<<<BB, 1024>>>(o_dist, vf, o_idx);
    k_post<<<PB, PTHR, PSMEM>>>(in_w, in_b, out_w, out_b, o_ref, o_attn);
}

// round 15
// speedup vs baseline: 1.1206x; 1.0022x over previous
#include <cuda_runtime.h>
#include <math.h>

#define BB 8
#define TT 8192
#define DV 1024
#define DQ 768
#define KREP 6
#define NH 8
#define HD 128
#define CC 18
#define NB 2048
#define NBLK 128
#define PB 148          // k_post blocks: 1/SM (192KB smem)
#define PTHR 512        // k_post threads (16 warps)
#define PSMEM (48 * DV * 4)   // 192KB dynamic smem

typedef unsigned long long ull;

// ---------------- scratch (no allocations allowed) ----------------
__device__ __align__(16) float g_pre[2 * BB * DV];
__device__ __align__(16) float g_h[2 * BB * DV];
__device__ __align__(16) float g_mu[BB * DV];
__device__ __align__(16) float g_isg[BB * DV];
__device__ __align__(16) float g_rep[BB * KREP * DV];
__device__ __align__(16) float g_qkv[BB * KREP * 3 * DV];
__device__ __align__(16) float g_ao[BB * KREP * DV];
__device__ float g_attnw[BB * NH * KREP * KREP];
__device__ unsigned g_cnt = 0, g_gen = 0;

__device__ __forceinline__ float warp_sum(float v) {
#pragma unroll
    for (int o = 16; o; o >>= 1) v += __shfl_xor_sync(0xffffffffu, v, o);
    return v;
}

__device__ __forceinline__ ull pack2(float a, float b) {
    ull r;
    asm("mov.b64 %0, {%1, %2};" : "=l"(r) : "f"(a), "f"(b));
    return r;
}
__device__ __forceinline__ ull fma2(ull a, ull b, ull c) {
    ull d;
    asm("fma.rn.f32x2 %0, %1, %2, %3;" : "=l"(d) : "l"(a), "l"(b), "l"(c));
    return d;
}
__device__ __forceinline__ void unpack2(ull v, float& lo, float& hi) {
    asm("mov.b64 {%0, %1}, %2;" : "=f"(lo), "=f"(hi) : "l"(v));
}

// software grid barrier: nblk blocks, all co-resident
__device__ __forceinline__ void gbar(unsigned nblk) {
    __syncthreads();
    if (threadIdx.x == 0) {
        volatile unsigned* vgen = &g_gen;
        unsigned gen = *vgen;
        __threadfence();
        unsigned t = atomicAdd(&g_cnt, 1u);
        if (t == nblk - 1) {
            atomicExch(&g_cnt, 0u);
            __threadfence();
            atomicAdd(&g_gen, 1u);
        } else {
            while (*vgen == gen) { }
            __threadfence();
        }
    }
    __syncthreads();
}

// ================= kernel 1: MLP (lin1 -> LN -> lin2), persistent =================
__global__ __launch_bounds__(512, 1) void k_mlp(
    const float* __restrict__ qe,
    const float* __restrict__ mu_w1, const float* __restrict__ mu_b1,
    const float* __restrict__ mu_g,  const float* __restrict__ mu_bt,
    const float* __restrict__ mu_w2, const float* __restrict__ mu_b2,
    const float* __restrict__ sg_w1, const float* __restrict__ sg_b1,
    const float* __restrict__ sg_g,  const float* __restrict__ sg_bt,
    const float* __restrict__ sg_w2, const float* __restrict__ sg_b2,
    float* __restrict__ o_mu, float* __restrict__ o_sg) {

    __shared__ float red[16];
    __shared__ float sh_mean, sh_rstd;
    int tid = threadIdx.x, lane = tid & 31, wid = tid >> 5, blk = blockIdx.x;

    {
        int gw = blk * 16 + wid;  // 0..2047
#pragma unroll
        for (int d = 0; d < 8; d++) {
            int idx = gw * 8 + d;
            int br = idx >> 13;
            int rem = idx & 8191;
            int b = rem >> 10, o = rem & 1023;
            const float* w1 = br ? sg_w1 : mu_w1;
            const float* b1 = br ? sg_b1 : mu_b1;
            const float* x = qe + b * DQ;
            const float* wr = w1 + o * DQ;
            float acc = 0.f;
#pragma unroll
            for (int i = lane; i < DQ; i += 32) acc += wr[i] * x[i];
            acc = warp_sum(acc);
            if (lane == 0) g_pre[(br * BB + b) * DV + o] = acc + b1[o];
        }
    }
    gbar(NBLK);

    if (blk < 16) {
        int b = blk >> 1, br = blk & 1;
        const float* src = g_pre + (br * BB + b) * DV;
        float v0 = src[tid], v1 = src[tid + 512];
        float s = warp_sum(v0 + v1);
        if (lane == 0) red[wid] = s;
        __syncthreads();
        if (tid == 0) {
            float m = 0.f;
            for (int i = 0; i < 16; i++) m += red[i];
            sh_mean = m / (float)DV;
        }
        __syncthreads();
        float m = sh_mean;
        float d0 = v0 - m, d1 = v1 - m;
        float vv = warp_sum(d0 * d0 + d1 * d1);
        if (lane == 0) red[wid] = vv;
        __syncthreads();
        if (tid == 0) {
            float q = 0.f;
            for (int i = 0; i < 16; i++) q += red[i];
            sh_rstd = rsqrtf(q / (float)DV + 1e-5f);
        }
        __syncthreads();
        float rstd = sh_rstd;
        const float* g  = br ? sg_g  : mu_g;
        const float* bt = br ? sg_bt : mu_bt;
        float* dst = g_h + (br * BB + b) * DV;
        dst[tid]       = fmaxf(d0 * rstd * g[tid]       + bt[tid], 0.f);
        dst[tid + 512] = fmaxf(d1 * rstd * g[tid + 512] + bt[tid + 512], 0.f);
    }
    gbar(NBLK);

    {
        int gw = blk * 16 + wid;
#pragma unroll
        for (int d = 0; d < 8; d++) {
            int idx = gw * 8 + d;
            int br = idx >> 13;
            int rem = idx & 8191;
            int b = rem >> 10, o = rem & 1023;
            const float* w2 = br ? sg_w2 : mu_w2;
            const float* b2 = br ? sg_b2 : mu_b2;
            const float* x = g_h + (br * BB + b) * DV;
            const float* wr = w2 + o * DV;
            float acc = 0.f;
#pragma unroll
            for (int i = lane; i < DV; i += 32) acc += wr[i] * x[i];
            acc = warp_sum(acc);
            if (lane == 0) {
                float val = acc + b2[o];
                if (br == 0) {
                    g_mu[b * DV + o] = val;
                    o_mu[b * DV + o] = val;
                } else {
                    float sp = fmaxf(val, 0.f) + log1pf(expf(-fabsf(val)));
                    float sg = sp + 1e-6f;
                    o_sg[b * DV + o] = sg;
                    g_isg[b * DV + o] = 1.f / sg;
                }
            }
        }
    }
}

// ================= kernel 2: Mahalanobis distance, 4 rows/warp =================
__global__ void k_dist(const float* __restrict__ vf, float* __restrict__ o_dist) {
    __shared__ float4 mus[DV / 4];
    __shared__ float4 iss[DV / 4];
    int b = blockIdx.y;
    int tid = threadIdx.x, lane = tid & 31, wid = tid >> 5;
    if (tid < 256) mus[tid] = ((const float4*)(g_mu + b * DV))[tid];
    else           iss[tid - 256] = ((const float4*)(g_isg + b * DV))[tid - 256];
    __syncthreads();

    int t0 = (blockIdx.x * 16 + wid) * 4;
    const float4* v0 = (const float4*)(vf + ((size_t)b * TT + t0) * DV);
    const float4* v1 = v0 + DV / 4;
    const float4* v2 = v1 + DV / 4;
    const float4* v3 = v2 + DV / 4;
    float a0 = 0.f, a1 = 0.f, a2 = 0.f, a3 = 0.f;
#pragma unroll
    for (int it = 0; it < 8; it++) {
        int i = lane + it * 32;
        float4 x0 = v0[i], x1 = v1[i], x2 = v2[i], x3 = v3[i];
        float4 mm = mus[i], ss = iss[i];
        float d;
        d = x0.x - mm.x; a0 += d * d * ss.x;
        d = x0.y - mm.y; a0 += d * d * ss.y;
        d = x0.z - mm.z; a0 += d * d * ss.z;
        d = x0.w - mm.w; a0 += d * d * ss.w;
        d = x1.x - mm.x; a1 += d * d * ss.x;
        d = x1.y - mm.y; a1 += d * d * ss.y;
        d = x1.z - mm.z; a1 += d * d * ss.z;
        d = x1.w - mm.w; a1 += d * d * ss.w;
        d = x2.x - mm.x; a2 += d * d * ss.x;
        d = x2.y - mm.y; a2 += d * d * ss.y;
        d = x2.z - mm.z; a2 += d * d * ss.z;
        d = x2.w - mm.w; a2 += d * d * ss.w;
        d = x3.x - mm.x; a3 += d * d * ss.x;
        d = x3.y - mm.y; a3 += d * d * ss.y;
        d = x3.z - mm.z; a3 += d * d * ss.z;
        d = x3.w - mm.w; a3 += d * d * ss.w;
    }
    a0 = warp_sum(a0);
    a1 = warp_sum(a1);
    a2 = warp_sum(a2);
    a3 = warp_sum(a3);
    if (lane == 0) {
        o_dist[b * TT + t0]     = a0;
        o_dist[b * TT + t0 + 1] = a1;
        o_dist[b * TT + t0 + 2] = a2;
        o_dist[b * TT + t0 + 3] = a3;
    }
}

// ================= kernel 3: select (proven, 8 x 1024) =================
__device__ void radix_pass_s(const unsigned* __restrict__ keys,
                             int shift, int bits, bool first,
                             unsigned* hist, unsigned* wsum, unsigned* wpfx,
                             unsigned* sh_prefix, int* sh_k) {
    int tid = threadIdx.x, lane = tid & 31, wid = tid >> 5;
    hist[tid] = 0u;
    hist[tid + 1024] = 0u;
    __syncthreads();
    unsigned pfx = *sh_prefix;
    unsigned mask = (1u << bits) - 1u;
#pragma unroll
    for (int r = 0; r < 8; r++) {
        unsigned key = keys[tid + r * 1024];
        bool ok = first || ((key >> (shift + bits)) == pfx);
        if (ok) atomicAdd(&hist[(key >> shift) & mask], 1u);
    }
    __syncthreads();
    unsigned s0 = hist[tid * 2], s1 = hist[tid * 2 + 1];
    unsigned s = s0 + s1;
    unsigned inc = s;
#pragma unroll
    for (int o = 1; o < 32; o <<= 1) {
        unsigned n = __shfl_up_sync(0xffffffffu, inc, o);
        if (lane >= o) inc += n;
    }
    if (lane == 31) wsum[wid] = inc;
    __syncthreads();
    if (wid == 0) {
        unsigned v = wsum[lane];
        unsigned iw = v;
#pragma unroll
        for (int o = 1; o < 32; o <<= 1) {
            unsigned n = __shfl_up_sync(0xffffffffu, iw, o);
            if (lane >= o) iw += n;
        }
        wpfx[lane] = iw - v;
    }
    __syncthreads();
    unsigned base = wpfx[wid] + (inc - s);
    unsigned k = (unsigned)*sh_k;
    if (k >= base && k < base + s) {
        int bin = tid * 2;
        unsigned off = base;
        if (k >= off + s0) { off += s0; bin++; }
        *sh_prefix = (pfx << bits) | (unsigned)bin;
        *sh_k = (int)(k - off);
    }
    __syncthreads();
}

__global__ void k_select(const float* __restrict__ dist, const float* __restrict__ vf,
                         float* __restrict__ o_idx) {
    __shared__ unsigned keys[TT];
    __shared__ unsigned hist[NB];
    __shared__ unsigned wsum[32], wpfx[32];
    __shared__ unsigned sh_prefix;
    __shared__ int sh_k;
    __shared__ unsigned long long lessK[CC];
    __shared__ int eqIdx[64];
    __shared__ int sh_nless, sh_neq;
    __shared__ int sels[KREP];

    int b = blockIdx.x;
    int tid = threadIdx.x;
    const float* drow = dist + b * TT;

#pragma unroll
    for (int r = 0; r < 8; r++)
        keys[tid + r * 1024] = __float_as_uint(drow[tid + r * 1024]);
    if (tid == 0) { sh_prefix = 0u; sh_k = (TT - 1) / 2; }
    __syncthreads();

    radix_pass_s(keys, 21, 11, true,  hist, wsum, wpfx, &sh_prefix, &sh_k);
    radix_pass_s(keys, 10, 11, false, hist, wsum, wpfx, &sh_prefix, &sh_k);
    radix_pass_s(keys,  0, 10, false, hist, wsum, wpfx, &sh_prefix, &sh_k);
    float med = __uint_as_float(sh_prefix);
    __syncthreads();

#pragma unroll
    for (int r = 0; r < 8; r++) {
        int i = tid + r * 1024;
        keys[i] = __float_as_uint(fabsf(__uint_as_float(keys[i]) - med));
    }
    if (tid == 0) { sh_prefix = 0u; sh_k = CC - 1; sh_nless = 0; sh_neq = 0; }
    __syncthreads();

    radix_pass_s(keys, 21, 11, true,  hist, wsum, wpfx, &sh_prefix, &sh_k);
    radix_pass_s(keys, 10, 11, false, hist, wsum, wpfx, &sh_prefix, &sh_k);
    radix_pass_s(keys,  0, 10, false, hist, wsum, wpfx, &sh_prefix, &sh_k);
    unsigned vstar = sh_prefix;
    int n_eq_take = sh_k + 1;
    __syncthreads();

#pragma unroll
    for (int r = 0; r < 8; r++) {
        int i = tid + r * 1024;
        unsigned key = keys[i];
        if (key < vstar) {
            int p = atomicAdd(&sh_nless, 1);
            lessK[p] = ((unsigned long long)key << 13) | (unsigned)i;
        } else if (key == vstar) {
            int p = atomicAdd(&sh_neq, 1);
            if (p < 64) eqIdx[p] = i;
        }
    }
    __syncthreads();

    if (tid == 0) {
        int nless = sh_nless;
        int neq = sh_neq < 64 ? sh_neq : 64;
        for (int i = 1; i < nless; i++) {
            unsigned long long kv = lessK[i];
            int j = i - 1;
            while (j >= 0 && lessK[j] > kv) { lessK[j + 1] = lessK[j]; j--; }
            lessK[j + 1] = kv;
        }
        for (int i = 1; i < neq; i++) {
            int kv = eqIdx[i];
            int j = i - 1;
            while (j >= 0 && eqIdx[j] > kv) { eqIdx[j + 1] = eqIdx[j]; j--; }
            eqIdx[j + 1] = kv;
        }
        int cand[CC];
        for (int c = 0; c < nless; c++) cand[c] = (int)(lessK[c] & 0x1FFFull);
        for (int c = 0; c < n_eq_take && nless + c < CC; c++) cand[nless + c] = eqIdx[c];

        const float NINF = __int_as_float(0xff800000);
        float candf[CC], mind[CC];
        int sel[KREP];
        for (int c = 0; c < CC; c++) candf[c] = (float)cand[c];
        for (int c = 0; c < CC; c++) mind[c] = fabsf(candf[c] - candf[0]);
        mind[0] = NINF;
        sel[0] = cand[0];
        for (int sI = 1; sI < KREP; sI++) {
            int best = 0;
            float bm = NINF;
            for (int c = 0; c < CC; c++)
                if (mind[c] > bm) { bm = mind[c]; best = c; }
            sel[sI] = cand[best];
            float cb = candf[best];
            for (int c = 0; c < CC; c++) mind[c] = fminf(mind[c], fabsf(candf[c] - cb));
            mind[best] = NINF;
        }
        for (int sI = 0; sI < KREP; sI++) {
            sels[sI] = sel[sI];
            o_idx[b * KREP + sI] = (float)sel[sI];
        }
    }
    __syncthreads();

    for (int kk = 0; kk < KREP; kk++) {
        int t = sels[kk];
        const float* src = vf + ((size_t)b * TT + t) * DV;
        float* dst = g_rep + (b * KREP + kk) * DV;
        if (tid < DV) dst[tid] = src[tid];
    }
}

// ================= kernel 4: post — row-pair f32x2 GEMM, x resident in smem ============
// smem x layout: 24 row-pairs x 1024 k, float4 f = {e[k],o[k],e[k+1],o[k+1]} at
// xs4[p*512 + kc*64 + fi], fi = (k - kc*128)/2. Lane-contiguous -> conflict-free LDS.128.
// Warp task = (2 outputs, 8 row-pairs). Per kc: 16 LDS.128 + 4 LDG.64(w) + 8 packs + 64 FFMA2.
__device__ void gemm_phase2(const float4* __restrict__ xs4, const float* __restrict__ w,
                            const float* __restrict__ bias, float* __restrict__ out,
                            int ostride, int nout) {
    int tid = threadIdx.x, lane = tid & 31, wid = tid >> 5;
    int og_count = nout >> 1;
    int ntask = og_count * 3;                  // 3 chunks of 8 row-pairs
    int gw = blockIdx.x * (PTHR / 32) + wid;
    const ulonglong2* xsu2 = (const ulonglong2*)xs4;
    for (int task = gw; task < ntask; task += PB * (PTHR / 32)) {
        int og = task % og_count, rch = task / og_count;
        int o0 = og * 2, pbase = rch * 8;
        const float2* wp0 = (const float2*)(w + (size_t)o0 * DV);
        const float2* wp1 = (const float2*)(w + (size_t)(o0 + 1) * DV);

        ull acc[2][8];
#pragma unroll
        for (int j = 0; j < 2; j++)
#pragma unroll
            for (int p = 0; p < 8; p++) acc[j][p] = 0ull;

        float2 w0a = wp0[lane], w0b = wp0[32 + lane];
        float2 w1a = wp1[lane], w1b = wp1[32 + lane];
#pragma unroll
        for (int kc = 0; kc < 8; kc++) {
            float2 n0a, n0b, n1a, n1b;
            if (kc < 7) {
                n0a = wp0[(kc + 1) * 64 + lane];      n0b = wp0[(kc + 1) * 64 + 32 + lane];
                n1a = wp1[(kc + 1) * 64 + lane];      n1b = wp1[(kc + 1) * 64 + 32 + lane];
            }
            // broadcast w into both packed halves
            ull w0a0 = pack2(w0a.x, w0a.x), w0a1 = pack2(w0a.y, w0a.y);
            ull w0b0 = pack2(w0b.x, w0b.x), w0b1 = pack2(w0b.y, w0b.y);
            ull w1a0 = pack2(w1a.x, w1a.x), w1a1 = pack2(w1a.y, w1a.y);
            ull w1b0 = pack2(w1b.x, w1b.x), w1b1 = pack2(w1b.y, w1b.y);
            const ulonglong2* xb = xsu2 + (size_t)pbase * 512 + kc * 64 + lane;
#pragma unroll
            for (int p = 0; p < 8; p++) {
                ulonglong2 ua = xb[(size_t)p * 512];        // k = kc*128 + 2*lane (+1)
                ulonglong2 ub = xb[(size_t)p * 512 + 32];   // k = kc*128 + 64 + 2*lane (+1)
                acc[0][p] = fma2(ua.x, w0a0, acc[0][p]);
                acc[0][p] = fma2(ua.y, w0a1, acc[0][p]);
                acc[0][p] = fma2(ub.x, w0b0, acc[0][p]);
                acc[0][p] = fma2(ub.y, w0b1, acc[0][p]);
                acc[1][p] = fma2(ua.x, w1a0, acc[1][p]);
                acc[1][p] = fma2(ua.y, w1a1, acc[1][p]);
                acc[1][p] = fma2(ub.x, w1b0, acc[1][p]);
                acc[1][p] = fma2(ub.y, w1b1, acc[1][p]);
            }
            if (kc < 7) { w0a = n0a; w0b = n0b; w1a = n1a; w1b = n1b; }
        }
        float bs0 = bias[o0], bs1 = bias[o0 + 1];
#pragma unroll
        for (int p = 0; p < 8; p++) {
            float e0, oo0, e1, oo1;
            unpack2(acc[0][p], e0, oo0);
            unpack2(acc[1][p], e1, oo1);
            e0 = warp_sum(e0);  oo0 = warp_sum(oo0);
            e1 = warp_sum(e1);  oo1 = warp_sum(oo1);
            if (lane == p) {
                int rowe = 2 * (pbase + p), rowo = rowe + 1;
                float* de = out + (size_t)rowe * ostride + o0;
                float* dо = out + (size_t)rowo * ostride + o0;
                de[0] = e0 + bs0;  de[1] = e1 + bs1;
                dо[0] = oo0 + bs0; dо[1] = oo1 + bs1;
            }
        }
    }
}

// stage x (48 x 1024 row-major) into paired smem layout
__device__ void stage_pairs(const float* __restrict__ x, float4* __restrict__ xs4) {
    int tid = threadIdx.x;
#pragma unroll
    for (int j = 0; j < 24; j++) {
        int idx = tid + j * PTHR;        // 12288 float4
        int p = idx >> 9, k2 = idx & 511;    // pair, k/2
        float2 e2 = ((const float2*)x)[(size_t)(2 * p) * 512 + k2];
        float2 o2 = ((const float2*)x)[(size_t)(2 * p + 1) * 512 + k2];
        xs4[idx] = make_float4(e2.x, o2.x, e2.y, o2.y);
    }
}

__global__ __launch_bounds__(PTHR, 1) void k_post(
    const float* __restrict__ in_w,  const float* __restrict__ in_b,
    const float* __restrict__ out_w, const float* __restrict__ out_b,
    float* __restrict__ o_ref, float* __restrict__ o_attn) {

    extern __shared__ __align__(16) float sdyn[];   // 192KB
    float4* xs4 = (float4*)sdyn;
    int tid = threadIdx.x, lane = tid & 31, wid = tid >> 5, blk = blockIdx.x;

    stage_pairs(g_rep, xs4);
    __syncthreads();

    // ---- P0: QKV GEMM (1536 ogroups x 3 chunks = 4608 tasks, 2 rounds) ----
    gemm_phase2(xs4, in_w, in_b, g_qkv, 3 * DV, 3 * DV);
    gbar(PB);

    // ---- P1: attention per (b,h) (blocks 0..63); tiles overlay sdyn ----
    if (blk < BB * NH) {
        int b = blk >> 3, h = blk & 7;
        float* qs = sdyn;
        float* ks = sdyn + KREP * HD;
        float* vs = sdyn + 2 * KREP * HD;
        for (int i = tid; i < KREP * HD; i += PTHR) {
            int row = i >> 7, d = i & 127;
            const float* base = g_qkv + (b * KREP + row) * 3 * DV + h * HD + d;
            qs[i] = base[0];
            ks[i] = base[DV];
            vs[i] = base[2 * DV];
        }
        __syncthreads();
        if (wid < KREP) {
            int i = wid;
            float sc[KREP];
            const float scale = 0.08838834764831845f;  // 1/sqrt(128)
            for (int j = 0; j < KREP; j++) {
                float acc = 0.f;
#pragma unroll
                for (int m = 0; m < 4; m++)
                    acc += qs[i * HD + lane + 32 * m] * ks[j * HD + lane + 32 * m];
                acc = warp_sum(acc);
                sc[j] = acc * scale;
            }
            float mx = sc[0];
            for (int j = 1; j < KREP; j++) mx = fmaxf(mx, sc[j]);
            float den = 0.f;
            for (int j = 0; j < KREP; j++) { sc[j] = expf(sc[j] - mx); den += sc[j]; }
            float rden = 1.f / den;
            for (int j = 0; j < KREP; j++) sc[j] *= rden;
            if (lane < KREP)
                g_attnw[((b * NH + h) * KREP + i) * KREP + lane] = sc[lane];
            for (int d = lane; d < HD; d += 32) {
                float o = 0.f;
                for (int j = 0; j < KREP; j++) o += sc[j] * vs[j * HD + d];
                g_ao[(b * KREP + i) * DV + h * HD + d] = o;
            }
        }
    }
    gbar(PB);

    // ---- P2: attn head-mean (blocks 64..71), restage x = g_ao, oproj ----
    if (blk >= 64 && blk < 64 + BB && tid < KREP * KREP) {
        int b = blk - 64;
        float s = 0.f;
        for (int h = 0; h < NH; h++) s += g_attnw[(b * NH + h) * KREP * KREP + tid];
        o_attn[b * KREP * KREP + tid] = s * (1.f / (float)NH);
    }
    __syncthreads();
    stage_pairs(g_ao, xs4);
    __syncthreads();
    gemm_phase2(xs4, out_w, out_b, o_ref, DV, DV);
}

// ---------------- launcher ----------------
extern "C" void kernel_launch(void* const* d_in, const int* in_sizes, int n_in,
                              void* d_out, int out_size) {
    const float* vf    = (const float*)d_in[0];
    const float* qe    = (const float*)d_in[1];
    const float* mu_w1 = (const float*)d_in[2];
    const float* mu_b1 = (const float*)d_in[3];
    const float* mu_g  = (const float*)d_in[4];
    const float* mu_bt = (const float*)d_in[5];
    const float* mu_w2 = (const float*)d_in[6];
    const float* mu_b2 = (const float*)d_in[7];
    const float* sg_w1 = (const float*)d_in[8];
    const float* sg_b1 = (const float*)d_in[9];
    const float* sg_g  = (const float*)d_in[10];
    const float* sg_bt = (const float*)d_in[11];
    const float* sg_w2 = (const float*)d_in[12];
    const float* sg_b2 = (const float*)d_in[13];
    const float* in_w  = (const float*)d_in[14];
    const float* in_b  = (const float*)d_in[15];
    const float* out_w = (const float*)d_in[16];
    const float* out_b = (const float*)d_in[17];

    float* out = (float*)d_out;
    float* o_ref  = out;           // [8,6,1024]  49152
    float* o_idx  = out + 49152;   // [8,6]       48
    float* o_dist = out + 49200;   // [8,8192]    65536
    float* o_mu   = out + 114736;  // [8,1024]    8192
    float* o_sg   = out + 122928;  // [8,1024]    8192
    float* o_attn = out + 131120;  // [8,6,6]     288

    static int attr_set = 0;
    if (!attr_set) {
        cudaFuncSetAttribute(k_post, cudaFuncAttributeMaxDynamicSharedMemorySize, PSMEM);
        attr_set = 1;
    }

    k_mlp<<<NBLK, 512>>>(qe, mu_w1, mu_b1, mu_g, mu_bt, mu_w2, mu_b2,
                         sg_w1, sg_b1, sg_g, sg_bt, sg_w2, sg_b2, o_mu, o_sg);
    k_dist<<<dim3(TT / 64, BB), 512>>>(vf, o_dist);
    k_select<<<BB, 1024>>>(o_dist, vf, o_idx);
    k_post<<<PB, PTHR, PSMEM>>>(in_w, in_b, out_w, out_b, o_ref, o_attn);
}

// round 16
// speedup vs baseline: 1.2071x; 1.0772x over previous
#include <cuda_runtime.h>
#include <math.h>

#define BB 8
#define TT 8192
#define DV 1024
#define DQ 768
#define KREP 6
#define NH 8
#define HD 128
#define CC 18
#define NB 2048
#define NBLK 128
#define PB 148          // k_post blocks: 1/SM (192KB smem)
#define PTHR 512        // k_post threads (16 warps)
#define PSMEM (48 * DV * 4)   // 192KB dynamic smem

typedef unsigned long long ull;

// ---------------- scratch (no allocations allowed) ----------------
__device__ __align__(16) float g_pre[2 * BB * DV];
__device__ __align__(16) float g_h[2 * BB * DV];
__device__ __align__(16) float g_mu[BB * DV];
__device__ __align__(16) float g_isg[BB * DV];
__device__ __align__(16) float g_rep[BB * KREP * DV];
__device__ __align__(16) float g_qkv[BB * KREP * 3 * DV];
__device__ __align__(16) float g_ao[BB * KREP * DV];
__device__ float g_attnw[BB * NH * KREP * KREP];
__device__ unsigned g_cnt = 0, g_gen = 0;

__device__ __forceinline__ float warp_sum(float v) {
#pragma unroll
    for (int o = 16; o; o >>= 1) v += __shfl_xor_sync(0xffffffffu, v, o);
    return v;
}

__device__ __forceinline__ ull pack2(float a, float b) {
    ull r;
    asm("mov.b64 %0, {%1, %2};" : "=l"(r) : "f"(a), "f"(b));
    return r;
}
__device__ __forceinline__ ull fma2(ull a, ull b, ull c) {
    ull d;
    asm("fma.rn.f32x2 %0, %1, %2, %3;" : "=l"(d) : "l"(a), "l"(b), "l"(c));
    return d;
}
__device__ __forceinline__ void unpack2(ull v, float& lo, float& hi) {
    asm("mov.b64 {%0, %1}, %2;" : "=f"(lo), "=f"(hi) : "l"(v));
}

// software grid barrier: nblk blocks, all co-resident
__device__ __forceinline__ void gbar(unsigned nblk) {
    __syncthreads();
    if (threadIdx.x == 0) {
        volatile unsigned* vgen = &g_gen;
        unsigned gen = *vgen;
        __threadfence();
        unsigned t = atomicAdd(&g_cnt, 1u);
        if (t == nblk - 1) {
            atomicExch(&g_cnt, 0u);
            __threadfence();
            atomicAdd(&g_gen, 1u);
        } else {
            while (*vgen == gen) { }
            __threadfence();
        }
    }
    __syncthreads();
}

// ================= kernel 1: MLP (lin1 -> LN -> lin2), persistent =================
__global__ __launch_bounds__(512, 1) void k_mlp(
    const float* __restrict__ qe,
    const float* __restrict__ mu_w1, const float* __restrict__ mu_b1,
    const float* __restrict__ mu_g,  const float* __restrict__ mu_bt,
    const float* __restrict__ mu_w2, const float* __restrict__ mu_b2,
    const float* __restrict__ sg_w1, const float* __restrict__ sg_b1,
    const float* __restrict__ sg_g,  const float* __restrict__ sg_bt,
    const float* __restrict__ sg_w2, const float* __restrict__ sg_b2,
    float* __restrict__ o_mu, float* __restrict__ o_sg) {

    __shared__ float red[16];
    __shared__ float sh_mean, sh_rstd;
    int tid = threadIdx.x, lane = tid & 31, wid = tid >> 5, blk = blockIdx.x;

    {
        int gw = blk * 16 + wid;  // 0..2047
#pragma unroll
        for (int d = 0; d < 8; d++) {
            int idx = gw * 8 + d;
            int br = idx >> 13;
            int rem = idx & 8191;
            int b = rem >> 10, o = rem & 1023;
            const float* w1 = br ? sg_w1 : mu_w1;
            const float* b1 = br ? sg_b1 : mu_b1;
            const float* x = qe + b * DQ;
            const float* wr = w1 + o * DQ;
            float acc = 0.f;
#pragma unroll
            for (int i = lane; i < DQ; i += 32) acc += wr[i] * x[i];
            acc = warp_sum(acc);
            if (lane == 0) g_pre[(br * BB + b) * DV + o] = acc + b1[o];
        }
    }
    gbar(NBLK);

    if (blk < 16) {
        int b = blk >> 1, br = blk & 1;
        const float* src = g_pre + (br * BB + b) * DV;
        float v0 = src[tid], v1 = src[tid + 512];
        float s = warp_sum(v0 + v1);
        if (lane == 0) red[wid] = s;
        __syncthreads();
        if (tid == 0) {
            float m = 0.f;
            for (int i = 0; i < 16; i++) m += red[i];
            sh_mean = m / (float)DV;
        }
        __syncthreads();
        float m = sh_mean;
        float d0 = v0 - m, d1 = v1 - m;
        float vv = warp_sum(d0 * d0 + d1 * d1);
        if (lane == 0) red[wid] = vv;
        __syncthreads();
        if (tid == 0) {
            float q = 0.f;
            for (int i = 0; i < 16; i++) q += red[i];
            sh_rstd = rsqrtf(q / (float)DV + 1e-5f);
        }
        __syncthreads();
        float rstd = sh_rstd;
        const float* g  = br ? sg_g  : mu_g;
        const float* bt = br ? sg_bt : mu_bt;
        float* dst = g_h + (br * BB + b) * DV;
        dst[tid]       = fmaxf(d0 * rstd * g[tid]       + bt[tid], 0.f);
        dst[tid + 512] = fmaxf(d1 * rstd * g[tid + 512] + bt[tid + 512], 0.f);
    }
    gbar(NBLK);

    {
        int gw = blk * 16 + wid;
#pragma unroll
        for (int d = 0; d < 8; d++) {
            int idx = gw * 8 + d;
            int br = idx >> 13;
            int rem = idx & 8191;
            int b = rem >> 10, o = rem & 1023;
            const float* w2 = br ? sg_w2 : mu_w2;
            const float* b2 = br ? sg_b2 : mu_b2;
            const float* x = g_h + (br * BB + b) * DV;
            const float* wr = w2 + o * DV;
            float acc = 0.f;
#pragma unroll
            for (int i = lane; i < DV; i += 32) acc += wr[i] * x[i];
            acc = warp_sum(acc);
            if (lane == 0) {
                float val = acc + b2[o];
                if (br == 0) {
                    g_mu[b * DV + o] = val;
                    o_mu[b * DV + o] = val;
                } else {
                    float sp = fmaxf(val, 0.f) + log1pf(expf(-fabsf(val)));
                    float sg = sp + 1e-6f;
                    o_sg[b * DV + o] = sg;
                    g_isg[b * DV + o] = 1.f / sg;
                }
            }
        }
    }
}

// ================= kernel 2: Mahalanobis distance, 2 rows/warp (proven best) =========
__global__ void k_dist(const float* __restrict__ vf, float* __restrict__ o_dist) {
    __shared__ float4 mus[DV / 4];
    __shared__ float4 iss[DV / 4];
    int b = blockIdx.y;
    int tid = threadIdx.x, lane = tid & 31, wid = tid >> 5;
    if (tid < 256) mus[tid] = ((const float4*)(g_mu + b * DV))[tid];
    else           iss[tid - 256] = ((const float4*)(g_isg + b * DV))[tid - 256];
    __syncthreads();

    int t0 = (blockIdx.x * 16 + wid) * 2;
    const float4* v0 = (const float4*)(vf + ((size_t)b * TT + t0) * DV);
    const float4* v1 = v0 + DV / 4;
    float a0 = 0.f, a1 = 0.f;
#pragma unroll
    for (int it = 0; it < 8; it++) {
        int i = lane + it * 32;
        float4 x0 = v0[i], x1 = v1[i], mm = mus[i], ss = iss[i];
        float d;
        d = x0.x - mm.x; a0 += d * d * ss.x;
        d = x0.y - mm.y; a0 += d * d * ss.y;
        d = x0.z - mm.z; a0 += d * d * ss.z;
        d = x0.w - mm.w; a0 += d * d * ss.w;
        d = x1.x - mm.x; a1 += d * d * ss.x;
        d = x1.y - mm.y; a1 += d * d * ss.y;
        d = x1.z - mm.z; a1 += d * d * ss.z;
        d = x1.w - mm.w; a1 += d * d * ss.w;
    }
    a0 = warp_sum(a0);
    a1 = warp_sum(a1);
    if (lane == 0) {
        o_dist[b * TT + t0]     = a0;
        o_dist[b * TT + t0 + 1] = a1;
    }
}

// ================= kernel 3: select (proven, 8 x 1024) =================
__device__ void radix_pass_s(const unsigned* __restrict__ keys,
                             int shift, int bits, bool first,
                             unsigned* hist, unsigned* wsum, unsigned* wpfx,
                             unsigned* sh_prefix, int* sh_k) {
    int tid = threadIdx.x, lane = tid & 31, wid = tid >> 5;
    hist[tid] = 0u;
    hist[tid + 1024] = 0u;
    __syncthreads();
    unsigned pfx = *sh_prefix;
    unsigned mask = (1u << bits) - 1u;
#pragma unroll
    for (int r = 0; r < 8; r++) {
        unsigned key = keys[tid + r * 1024];
        bool ok = first || ((key >> (shift + bits)) == pfx);
        if (ok) atomicAdd(&hist[(key >> shift) & mask], 1u);
    }
    __syncthreads();
    unsigned s0 = hist[tid * 2], s1 = hist[tid * 2 + 1];
    unsigned s = s0 + s1;
    unsigned inc = s;
#pragma unroll
    for (int o = 1; o < 32; o <<= 1) {
        unsigned n = __shfl_up_sync(0xffffffffu, inc, o);
        if (lane >= o) inc += n;
    }
    if (lane == 31) wsum[wid] = inc;
    __syncthreads();
    if (wid == 0) {
        unsigned v = wsum[lane];
        unsigned iw = v;
#pragma unroll
        for (int o = 1; o < 32; o <<= 1) {
            unsigned n = __shfl_up_sync(0xffffffffu, iw, o);
            if (lane >= o) iw += n;
        }
        wpfx[lane] = iw - v;
    }
    __syncthreads();
    unsigned base = wpfx[wid] + (inc - s);
    unsigned k = (unsigned)*sh_k;
    if (k >= base && k < base + s) {
        int bin = tid * 2;
        unsigned off = base;
        if (k >= off + s0) { off += s0; bin++; }
        *sh_prefix = (pfx << bits) | (unsigned)bin;
        *sh_k = (int)(k - off);
    }
    __syncthreads();
}

__global__ void k_select(const float* __restrict__ dist, const float* __restrict__ vf,
                         float* __restrict__ o_idx) {
    __shared__ unsigned keys[TT];
    __shared__ unsigned hist[NB];
    __shared__ unsigned wsum[32], wpfx[32];
    __shared__ unsigned sh_prefix;
    __shared__ int sh_k;
    __shared__ unsigned long long lessK[CC];
    __shared__ int eqIdx[64];
    __shared__ int sh_nless, sh_neq;
    __shared__ int sels[KREP];

    int b = blockIdx.x;
    int tid = threadIdx.x;
    const float* drow = dist + b * TT;

#pragma unroll
    for (int r = 0; r < 8; r++)
        keys[tid + r * 1024] = __float_as_uint(drow[tid + r * 1024]);
    if (tid == 0) { sh_prefix = 0u; sh_k = (TT - 1) / 2; }
    __syncthreads();

    radix_pass_s(keys, 21, 11, true,  hist, wsum, wpfx, &sh_prefix, &sh_k);
    radix_pass_s(keys, 10, 11, false, hist, wsum, wpfx, &sh_prefix, &sh_k);
    radix_pass_s(keys,  0, 10, false, hist, wsum, wpfx, &sh_prefix, &sh_k);
    float med = __uint_as_float(sh_prefix);
    __syncthreads();

#pragma unroll
    for (int r = 0; r < 8; r++) {
        int i = tid + r * 1024;
        keys[i] = __float_as_uint(fabsf(__uint_as_float(keys[i]) - med));
    }
    if (tid == 0) { sh_prefix = 0u; sh_k = CC - 1; sh_nless = 0; sh_neq = 0; }
    __syncthreads();

    radix_pass_s(keys, 21, 11, true,  hist, wsum, wpfx, &sh_prefix, &sh_k);
    radix_pass_s(keys, 10, 11, false, hist, wsum, wpfx, &sh_prefix, &sh_k);
    radix_pass_s(keys,  0, 10, false, hist, wsum, wpfx, &sh_prefix, &sh_k);
    unsigned vstar = sh_prefix;
    int n_eq_take = sh_k + 1;
    __syncthreads();

#pragma unroll
    for (int r = 0; r < 8; r++) {
        int i = tid + r * 1024;
        unsigned key = keys[i];
        if (key < vstar) {
            int p = atomicAdd(&sh_nless, 1);
            lessK[p] = ((unsigned long long)key << 13) | (unsigned)i;
        } else if (key == vstar) {
            int p = atomicAdd(&sh_neq, 1);
            if (p < 64) eqIdx[p] = i;
        }
    }
    __syncthreads();

    if (tid == 0) {
        int nless = sh_nless;
        int neq = sh_neq < 64 ? sh_neq : 64;
        for (int i = 1; i < nless; i++) {
            unsigned long long kv = lessK[i];
            int j = i - 1;
            while (j >= 0 && lessK[j] > kv) { lessK[j + 1] = lessK[j]; j--; }
            lessK[j + 1] = kv;
        }
        for (int i = 1; i < neq; i++) {
            int kv = eqIdx[i];
            int j = i - 1;
            while (j >= 0 && eqIdx[j] > kv) { eqIdx[j + 1] = eqIdx[j]; j--; }
            eqIdx[j + 1] = kv;
        }
        int cand[CC];
        for (int c = 0; c < nless; c++) cand[c] = (int)(lessK[c] & 0x1FFFull);
        for (int c = 0; c < n_eq_take && nless + c < CC; c++) cand[nless + c] = eqIdx[c];

        const float NINF = __int_as_float(0xff800000);
        float candf[CC], mind[CC];
        int sel[KREP];
        for (int c = 0; c < CC; c++) candf[c] = (float)cand[c];
        for (int c = 0; c < CC; c++) mind[c] = fabsf(candf[c] - candf[0]);
        mind[0] = NINF;
        sel[0] = cand[0];
        for (int sI = 1; sI < KREP; sI++) {
            int best = 0;
            float bm = NINF;
            for (int c = 0; c < CC; c++)
                if (mind[c] > bm) { bm = mind[c]; best = c; }
            sel[sI] = cand[best];
            float cb = candf[best];
            for (int c = 0; c < CC; c++) mind[c] = fminf(mind[c], fabsf(candf[c] - cb));
            mind[best] = NINF;
        }
        for (int sI = 0; sI < KREP; sI++) {
            sels[sI] = sel[sI];
            o_idx[b * KREP + sI] = (float)sel[sI];
        }
    }
    __syncthreads();

    for (int kk = 0; kk < KREP; kk++) {
        int t = sels[kk];
        const float* src = vf + ((size_t)b * TT + t) * DV;
        float* dst = g_rep + (b * KREP + kk) * DV;
        if (tid < DV) dst[tid] = src[tid];
    }
}

// ================= kernel 4: post — row-pair f32x2 GEMM, 4 outputs x 4 pairs ==========
// smem x layout: pair p, float4 {e[k],o[k],e[k+1],o[k+1]} at xs4[p*512 + kc*64 + (k%128)/2].
// Warp task = (4 outputs, 4 row-pairs). Per kc: 8 LDS.128 + 8 LDG.64(w) + 16 packs + 64 FFMA2.
// Crossbar (512 cyc/kc/SM) == FFMA2 issue (512): balanced.
__device__ void gemm_phase2(const float4* __restrict__ xs4, const float* __restrict__ w,
                            const float* __restrict__ bias, float* __restrict__ out,
                            int ostride, int nout) {
    int tid = threadIdx.x, lane = tid & 31, wid = tid >> 5;
    int og_count = nout >> 2;
    int ntask = og_count * 6;                  // 6 chunks of 4 row-pairs
    int gw = blockIdx.x * (PTHR / 32) + wid;
    const ulonglong2* xsu2 = (const ulonglong2*)xs4;
    for (int task = gw; task < ntask; task += PB * (PTHR / 32)) {
        int og = task % og_count, rch = task / og_count;
        int o0 = og * 4, pbase = rch * 4;
        const float2* wp[4];
#pragma unroll
        for (int j = 0; j < 4; j++) wp[j] = (const float2*)(w + (size_t)(o0 + j) * DV);

        ull acc[4][4];
#pragma unroll
        for (int j = 0; j < 4; j++)
#pragma unroll
            for (int p = 0; p < 4; p++) acc[j][p] = 0ull;

        float2 wa[4], wb[4];
#pragma unroll
        for (int j = 0; j < 4; j++) { wa[j] = wp[j][lane]; wb[j] = wp[j][32 + lane]; }
#pragma unroll
        for (int kc = 0; kc < 8; kc++) {
            float2 na[4], nb[4];
            if (kc < 7) {
#pragma unroll
                for (int j = 0; j < 4; j++) {
                    na[j] = wp[j][(kc + 1) * 64 + lane];
                    nb[j] = wp[j][(kc + 1) * 64 + 32 + lane];
                }
            }
            ull wA0[4], wA1[4], wB0[4], wB1[4];
#pragma unroll
            for (int j = 0; j < 4; j++) {
                wA0[j] = pack2(wa[j].x, wa[j].x);
                wA1[j] = pack2(wa[j].y, wa[j].y);
                wB0[j] = pack2(wb[j].x, wb[j].x);
                wB1[j] = pack2(wb[j].y, wb[j].y);
            }
            const ulonglong2* xb = xsu2 + (size_t)pbase * 512 + kc * 64 + lane;
#pragma unroll
            for (int p = 0; p < 4; p++) {
                ulonglong2 ua = xb[(size_t)p * 512];        // k = kc*128 + 2*lane (+1)
                ulonglong2 ub = xb[(size_t)p * 512 + 32];   // k = kc*128 + 64 + 2*lane (+1)
#pragma unroll
                for (int j = 0; j < 4; j++) {
                    acc[j][p] = fma2(ua.x, wA0[j], acc[j][p]);
                    acc[j][p] = fma2(ua.y, wA1[j], acc[j][p]);
                    acc[j][p] = fma2(ub.x, wB0[j], acc[j][p]);
                    acc[j][p] = fma2(ub.y, wB1[j], acc[j][p]);
                }
            }
            if (kc < 7) {
#pragma unroll
                for (int j = 0; j < 4; j++) { wa[j] = na[j]; wb[j] = nb[j]; }
            }
        }
        float bs[4];
#pragma unroll
        for (int j = 0; j < 4; j++) bs[j] = bias[o0 + j];
#pragma unroll
        for (int p = 0; p < 4; p++) {
#pragma unroll
            for (int j = 0; j < 4; j++) {
                float e, o;
                unpack2(acc[j][p], e, o);
                e = warp_sum(e);
                o = warp_sum(o);
                if (lane == p * 4 + j) {
                    int rowe = 2 * (pbase + p);
                    float* de = out + (size_t)rowe * ostride + o0 + j;
                    de[0] = e + bs[j];
                    de[ostride] = o + bs[j];
                }
            }
        }
    }
}

// stage x (48 x 1024 row-major) into paired smem layout
__device__ void stage_pairs(const float* __restrict__ x, float4* __restrict__ xs4) {
    int tid = threadIdx.x;
#pragma unroll
    for (int j = 0; j < 24; j++) {
        int idx = tid + j * PTHR;        // 12288 float4
        int p = idx >> 9, k2 = idx & 511;    // pair, k/2
        float2 e2 = ((const float2*)x)[(size_t)(2 * p) * 512 + k2];
        float2 o2 = ((const float2*)x)[(size_t)(2 * p + 1) * 512 + k2];
        xs4[idx] = make_float4(e2.x, o2.x, e2.y, o2.y);
    }
}

__global__ __launch_bounds__(PTHR, 1) void k_post(
    const float* __restrict__ in_w,  const float* __restrict__ in_b,
    const float* __restrict__ out_w, const float* __restrict__ out_b,
    float* __restrict__ o_ref, float* __restrict__ o_attn) {

    extern __shared__ __align__(16) float sdyn[];   // 192KB
    float4* xs4 = (float4*)sdyn;
    int tid = threadIdx.x, lane = tid & 31, wid = tid >> 5, blk = blockIdx.x;

    stage_pairs(g_rep, xs4);
    __syncthreads();

    // ---- P0: QKV GEMM (768 ogroups x 6 chunks = 4608 tasks) ----
    gemm_phase2(xs4, in_w, in_b, g_qkv, 3 * DV, 3 * DV);
    gbar(PB);

    // ---- P1: attention per (b,h) (blocks 0..63); tiles overlay sdyn ----
    if (blk < BB * NH) {
        int b = blk >> 3, h = blk & 7;
        float* qs = sdyn;
        float* ks = sdyn + KREP * HD;
        float* vs = sdyn + 2 * KREP * HD;
        for (int i = tid; i < KREP * HD; i += PTHR) {
            int row = i >> 7, d = i & 127;
            const float* base = g_qkv + (b * KREP + row) * 3 * DV + h * HD + d;
            qs[i] = base[0];
            ks[i] = base[DV];
            vs[i] = base[2 * DV];
        }
        __syncthreads();
        if (wid < KREP) {
            int i = wid;
            float sc[KREP];
            const float scale = 0.08838834764831845f;  // 1/sqrt(128)
            for (int j = 0; j < KREP; j++) {
                float acc = 0.f;
#pragma unroll
                for (int m = 0; m < 4; m++)
                    acc += qs[i * HD + lane + 32 * m] * ks[j * HD + lane + 32 * m];
                acc = warp_sum(acc);
                sc[j] = acc * scale;
            }
            float mx = sc[0];
            for (int j = 1; j < KREP; j++) mx = fmaxf(mx, sc[j]);
            float den = 0.f;
            for (int j = 0; j < KREP; j++) { sc[j] = expf(sc[j] - mx); den += sc[j]; }
            float rden = 1.f / den;
            for (int j = 0; j < KREP; j++) sc[j] *= rden;
            if (lane < KREP)
                g_attnw[((b * NH + h) * KREP + i) * KREP + lane] = sc[lane];
            for (int d = lane; d < HD; d += 32) {
                float o = 0.f;
                for (int j = 0; j < KREP; j++) o += sc[j] * vs[j * HD + d];
                g_ao[(b * KREP + i) * DV + h * HD + d] = o;
            }
        }
    }
    gbar(PB);

    // ---- P2: attn head-mean (blocks 64..71), restage x = g_ao, oproj ----
    if (blk >= 64 && blk < 64 + BB && tid < KREP * KREP) {
        int b = blk - 64;
        float s = 0.f;
        for (int h = 0; h < NH; h++) s += g_attnw[(b * NH + h) * KREP * KREP + tid];
        o_attn[b * KREP * KREP + tid] = s * (1.f / (float)NH);
    }
    __syncthreads();
    stage_pairs(g_ao, xs4);
    __syncthreads();
    gemm_phase2(xs4, out_w, out_b, o_ref, DV, DV);
}

// ---------------- launcher ----------------
extern "C" void kernel_launch(void* const* d_in, const int* in_sizes, int n_in,
                              void* d_out, int out_size) {
    const float* vf    = (const float*)d_in[0];
    const float* qe    = (const float*)d_in[1];
    const float* mu_w1 = (const float*)d_in[2];
    const float* mu_b1 = (const float*)d_in[3];
    const float* mu_g  = (const float*)d_in[4];
    const float* mu_bt = (const float*)d_in[5];
    const float* mu_w2 = (const float*)d_in[6];
    const float* mu_b2 = (const float*)d_in[7];
    const float* sg_w1 = (const float*)d_in[8];
    const float* sg_b1 = (const float*)d_in[9];
    const float* sg_g  = (const float*)d_in[10];
    const float* sg_bt = (const float*)d_in[11];
    const float* sg_w2 = (const float*)d_in[12];
    const float* sg_b2 = (const float*)d_in[13];
    const float* in_w  = (const float*)d_in[14];
    const float* in_b  = (const float*)d_in[15];
    const float* out_w = (const float*)d_in[16];
    const float* out_b = (const float*)d_in[17];

    float* out = (float*)d_out;
    float* o_ref  = out;           // [8,6,1024]  49152
    float* o_idx  = out + 49152;   // [8,6]       48
    float* o_dist = out + 49200;   // [8,8192]    65536
    float* o_mu   = out + 114736;  // [8,1024]    8192
    float* o_sg   = out + 122928;  // [8,1024]    8192
    float* o_attn = out + 131120;  // [8,6,6]     288

    static int attr_set = 0;
    if (!attr_set) {
        cudaFuncSetAttribute(k_post, cudaFuncAttributeMaxDynamicSharedMemorySize, PSMEM);
        attr_set = 1;
    }

    k_mlp<<<NBLK, 512>>>(qe, mu_w1, mu_b1, mu_g, mu_bt, mu_w2, mu_b2,
                         sg_w1, sg_b1, sg_g, sg_bt, sg_w2, sg_b2, o_mu, o_sg);
    k_dist<<<dim3(TT / 32, BB), 512>>>(vf, o_dist);
    k_select<<<BB, 1024>>>(o_dist, vf, o_idx);
    k_post<<<PB, PTHR, PSMEM>>>(in_w, in_b, out_w, out_b, o_ref, o_attn);
}